// round 10
// baseline (speedup 1.0000x reference)
#include <cuda_runtime.h>
#include <cuda_bf16.h>
#include <cstdint>

#define NN   3072
#define INF  512
#define NH   8
#define HD   64
#define OF   512   // NH*HD
#define MW   96    // mask words per row
#define KT   32    // attn j tile
#define MT   192   // attn i tile per CTA (6 warps x 32 i)
#define NTILES (NN / KT)
#define BROW 36    // B smem row pitch in floats (144B, conflict-free)

// ---------------- scratch ----------------
__device__ float         g_h[NN * OF];
__device__ float         g_P[NH * NN];
__device__ float         g_p[NH * NN];
__device__ float         g_Q[NH * NN];
__device__ float         g_q[NH * NN];
__device__ unsigned      g_mask[NN * MW];
__device__ float         g_hTf[NH * HD * NN];      // [h][d][n], tf32-rounded fp32
__device__ __nv_bfloat16 g_X1[NN * INF];
__device__ __nv_bfloat16 g_X2[NN * INF];
__device__ __nv_bfloat16 g_W1[OF * INF];
__device__ __nv_bfloat16 g_W2[OF * INF];

__device__ __forceinline__ uint32_t smem_u32(const void* p) {
    uint32_t a;
    asm("{ .reg .u64 t; cvta.to.shared.u64 t, %1; cvt.u32.u64 %0, t; }" : "=r"(a) : "l"(p));
    return a;
}

__device__ __forceinline__ void mma_bf16(float* c, const uint32_t* a, uint32_t b0, uint32_t b1) {
    asm volatile(
        "mma.sync.aligned.m16n8k16.row.col.f32.bf16.bf16.f32 "
        "{%0,%1,%2,%3}, {%4,%5,%6,%7}, {%8,%9}, {%0,%1,%2,%3};"
        : "+f"(c[0]), "+f"(c[1]), "+f"(c[2]), "+f"(c[3])
        : "r"(a[0]), "r"(a[1]), "r"(a[2]), "r"(a[3]), "r"(b0), "r"(b1));
}

__device__ __forceinline__ void mma_tf32(float* c, const uint32_t* a, uint32_t b0, uint32_t b1) {
    asm volatile(
        "mma.sync.aligned.m16n8k8.row.col.f32.tf32.tf32.f32 "
        "{%0,%1,%2,%3}, {%4,%5,%6,%7}, {%8,%9}, {%0,%1,%2,%3};"
        : "+f"(c[0]), "+f"(c[1]), "+f"(c[2]), "+f"(c[3])
        : "r"(a[0]), "r"(a[1]), "r"(a[2]), "r"(a[3]), "r"(b0), "r"(b1));
}

__device__ __forceinline__ void ldmx4(uint32_t* r, uint32_t addr) {
    asm volatile("ldmatrix.sync.aligned.m8n8.x4.shared.b16 {%0,%1,%2,%3}, [%4];"
                 : "=r"(r[0]), "=r"(r[1]), "=r"(r[2]), "=r"(r[3]) : "r"(addr));
}

__device__ __forceinline__ void split2(float w0, float w1, uint32_t& hi, uint32_t& lo) {
    uint32_t h;
    asm("cvt.rn.bf16x2.f32 %0, %1, %2;" : "=r"(h) : "f"(w1), "f"(w0));
    float r0 = w0 - __uint_as_float(h << 16);
    float r1 = w1 - __uint_as_float(h & 0xffff0000u);
    uint32_t l;
    asm("cvt.rn.bf16x2.f32 %0, %1, %2;" : "=r"(l) : "f"(r1), "f"(r0));
    hi = h; lo = l;
}

__device__ __forceinline__ uint32_t tf32r(float v) {
    uint32_t d;
    asm("cvt.rna.tf32.f32 %0, %1;" : "=r"(d) : "f"(v));
    return d;
}

// ---------------- Kernel 0: fp32 -> bf16 hi/lo split ----------------
__global__ __launch_bounds__(256) void fsplit_kernel(const float* __restrict__ src,
                                                     __nv_bfloat16* __restrict__ dhi,
                                                     __nv_bfloat16* __restrict__ dlo) {
    const int idx = (blockIdx.x * blockDim.x + threadIdx.x) * 4;
    float4 v = *(const float4*)(src + idx);
    uint32_t h0, h1, l0, l1;
    split2(v.x, v.y, h0, l0);
    split2(v.z, v.w, h1, l1);
    *(uint2*)(dhi + idx) = make_uint2(h0, h1);
    *(uint2*)(dlo + idx) = make_uint2(l0, l1);
}

// ---------------- Kernel 1: g_h = X @ W^T (bf16-split HMMA) ----------------
// CTA = 96m x 128n, BK=32, grid (32, 4) = 128 CTAs -> single wave.
__global__ __launch_bounds__(384) void gemm_kernel() {
    __shared__ __align__(16) unsigned char Ah[2][96 * 64];
    __shared__ __align__(16) unsigned char Al[2][96 * 64];
    __shared__ __align__(16) unsigned char Bh[2][128 * 64];
    __shared__ __align__(16) unsigned char Bl[2][128 * 64];

    const int tid = threadIdx.x;
    const int w   = tid >> 5;
    const int L   = tid & 31;
    const int bm  = blockIdx.x * 96;
    const int bn  = blockIdx.y * 128;

    const int arow   = tid >> 2;
    const int achunk = tid & 3;
    const uint32_t aoff = (uint32_t)(arow * 64 + ((achunk ^ ((arow >> 1) & 3)) << 4));
    const int brow0  = tid >> 2;
    const int bchunk = tid & 3;
    const uint32_t boff0 = (uint32_t)(brow0 * 64 + ((bchunk ^ ((brow0 >> 1) & 3)) << 4));
    const int brow1  = 96 + (tid >> 2);
    const uint32_t boff1 = (uint32_t)(brow1 * 64 + ((bchunk ^ ((brow1 >> 1) & 3)) << 4));
    const bool hasB1 = tid < 128;

    const int warp_m = (w >> 2) * 32;
    const int warp_n = (w & 3) * 32;

    float acc[2][4][4];
#pragma unroll
    for (int mg = 0; mg < 2; mg++)
#pragma unroll
        for (int ng = 0; ng < 4; ng++)
#pragma unroll
            for (int k = 0; k < 4; k++) acc[mg][ng][k] = 0.f;

    uint4 xa_h, xa_l, wb_h0, wb_l0, wb_h1, wb_l1;
    {
        const size_t ao = (size_t)(bm + arow) * INF + achunk * 8;
        xa_h = *(const uint4*)(g_X1 + ao);
        xa_l = *(const uint4*)(g_X2 + ao);
        const size_t bo0 = (size_t)(bn + brow0) * INF + bchunk * 8;
        wb_h0 = *(const uint4*)(g_W1 + bo0);
        wb_l0 = *(const uint4*)(g_W2 + bo0);
        if (hasB1) {
            const size_t bo1 = (size_t)(bn + brow1) * INF + bchunk * 8;
            wb_h1 = *(const uint4*)(g_W1 + bo1);
            wb_l1 = *(const uint4*)(g_W2 + bo1);
        }
    }

    for (int it = 0; it < INF / 32; it++) {
        const int buf = it & 1;
        *(uint4*)&Ah[buf][aoff]  = xa_h;
        *(uint4*)&Al[buf][aoff]  = xa_l;
        *(uint4*)&Bh[buf][boff0] = wb_h0;
        *(uint4*)&Bl[buf][boff0] = wb_l0;
        if (hasB1) {
            *(uint4*)&Bh[buf][boff1] = wb_h1;
            *(uint4*)&Bl[buf][boff1] = wb_l1;
        }
        __syncthreads();

        if (it + 1 < INF / 32) {
            const int k0 = (it + 1) * 32;
            const size_t ao = (size_t)(bm + arow) * INF + k0 + achunk * 8;
            xa_h = *(const uint4*)(g_X1 + ao);
            xa_l = *(const uint4*)(g_X2 + ao);
            const size_t bo0 = (size_t)(bn + brow0) * INF + k0 + bchunk * 8;
            wb_h0 = *(const uint4*)(g_W1 + bo0);
            wb_l0 = *(const uint4*)(g_W2 + bo0);
            if (hasB1) {
                const size_t bo1 = (size_t)(bn + brow1) * INF + k0 + bchunk * 8;
                wb_h1 = *(const uint4*)(g_W1 + bo1);
                wb_l1 = *(const uint4*)(g_W2 + bo1);
            }
        }

        const uint32_t aAh = smem_u32(&Ah[buf][0]);
        const uint32_t aAl = smem_u32(&Al[buf][0]);
        const uint32_t aBh = smem_u32(&Bh[buf][0]);
        const uint32_t aBl = smem_u32(&Bl[buf][0]);

        uint32_t bh[4][4], bl[4][4];
#pragma unroll
        for (int ng = 0; ng < 4; ng++) {
            const int row = warp_n + ng * 8 + (L & 7);
            const int ch  = L >> 3;
            const uint32_t off = (uint32_t)(row * 64 + ((ch ^ ((row >> 1) & 3)) << 4));
            ldmx4(bh[ng], aBh + off);
            ldmx4(bl[ng], aBl + off);
        }
        uint32_t ah[2][2][4], al[2][2][4];
#pragma unroll
        for (int mg = 0; mg < 2; mg++)
#pragma unroll
            for (int ks = 0; ks < 2; ks++) {
                const int mat = L >> 3;
                const int row = warp_m + mg * 16 + (L & 7) + (mat & 1) * 8;
                const int ch  = ks * 2 + (mat >> 1);
                const uint32_t off = (uint32_t)(row * 64 + ((ch ^ ((row >> 1) & 3)) << 4));
                ldmx4(ah[mg][ks], aAh + off);
                ldmx4(al[mg][ks], aAl + off);
            }

#pragma unroll
        for (int mg = 0; mg < 2; mg++)
#pragma unroll
            for (int ng = 0; ng < 4; ng++)
#pragma unroll
                for (int ks = 0; ks < 2; ks++) {
                    mma_bf16(acc[mg][ng], ah[mg][ks], bh[ng][2*ks], bh[ng][2*ks+1]);
                    mma_bf16(acc[mg][ng], ah[mg][ks], bl[ng][2*ks], bl[ng][2*ks+1]);
                    mma_bf16(acc[mg][ng], al[mg][ks], bh[ng][2*ks], bh[ng][2*ks+1]);
                }
        __syncthreads();
    }

#pragma unroll
    for (int mg = 0; mg < 2; mg++)
#pragma unroll
        for (int ng = 0; ng < 4; ng++) {
            const int row = bm + warp_m + mg * 16 + (L >> 2);
            const int col = bn + warp_n + ng * 8 + (L & 3) * 2;
            *(float2*)(g_h + (size_t)row * OF + col)       = make_float2(acc[mg][ng][0], acc[mg][ng][1]);
            *(float2*)(g_h + (size_t)(row + 8) * OF + col) = make_float2(acc[mg][ng][2], acc[mg][ng][3]);
        }
}

// ---------------- Kernel 3: adjacency (+diag) bitmask, MLP=2 ----------------
__global__ __launch_bounds__(256) void mask_kernel(const int* __restrict__ adj) {
    const int gw = (blockIdx.x * blockDim.x + threadIdx.x) >> 5;
    const int L  = threadIdx.x & 31;
    const int i  = gw / (NN / 256);
    const int sp = gw % (NN / 256);
    const int c0 = sp * 256 + L * 4;
    const int c1 = c0 + 128;
    const int4 v0 = *(const int4*)(adj + (size_t)i * NN + c0);
    const int4 v1 = *(const int4*)(adj + (size_t)i * NN + c1);
    unsigned nib0 = ((v0.x != 0 || c0     == i) ? 1u : 0u)
                  | ((v0.y != 0 || c0 + 1 == i) ? 2u : 0u)
                  | ((v0.z != 0 || c0 + 2 == i) ? 4u : 0u)
                  | ((v0.w != 0 || c0 + 3 == i) ? 8u : 0u);
    unsigned nib1 = ((v1.x != 0 || c1     == i) ? 1u : 0u)
                  | ((v1.y != 0 || c1 + 1 == i) ? 2u : 0u)
                  | ((v1.z != 0 || c1 + 2 == i) ? 4u : 0u)
                  | ((v1.w != 0 || c1 + 3 == i) ? 8u : 0u);
    unsigned a = nib0 << ((L & 7) * 4);
    unsigned b = nib1 << ((L & 7) * 4);
    a |= __shfl_xor_sync(0xffffffffu, a, 1);
    b |= __shfl_xor_sync(0xffffffffu, b, 1);
    a |= __shfl_xor_sync(0xffffffffu, a, 2);
    b |= __shfl_xor_sync(0xffffffffu, b, 2);
    a |= __shfl_xor_sync(0xffffffffu, a, 4);
    b |= __shfl_xor_sync(0xffffffffu, b, 4);
    if ((L & 7) == 0) {
        g_mask[i * MW + sp * 8 + (L >> 3)]     = a;
        g_mask[i * MW + sp * 8 + 4 + (L >> 3)] = b;
    }
}

// ---------------- Kernel 3b: fused transpose(tf32) + coef ----------------
__global__ __launch_bounds__(256) void htrans_kernel(const float* __restrict__ a_src,
                                                     const float* __restrict__ a_dst) {
    __shared__ float tl[32][65];
    const int h  = blockIdx.y;
    const int n0 = blockIdx.x * 32;
    const int t  = threadIdx.x;
    const int r  = t >> 3;
    const int c8 = (t & 7) * 8;
    {
        const float* src = g_h + (size_t)(n0 + r) * OF + h * HD + c8;
        float4 v0 = *(const float4*)src;
        float4 v1 = *(const float4*)(src + 4);
        tl[r][c8+0] = v0.x; tl[r][c8+1] = v0.y; tl[r][c8+2] = v0.z; tl[r][c8+3] = v0.w;
        tl[r][c8+4] = v1.x; tl[r][c8+5] = v1.y; tl[r][c8+6] = v1.z; tl[r][c8+7] = v1.w;

        const float4* as = (const float4*)(a_src + h * HD + c8);
        const float4* ad = (const float4*)(a_dst + h * HD + c8);
        float4 a0 = as[0], a1 = as[1], d0 = ad[0], d1 = ad[1];
        float s = v0.x*a0.x + v0.y*a0.y + v0.z*a0.z + v0.w*a0.w
                + v1.x*a1.x + v1.y*a1.y + v1.z*a1.z + v1.w*a1.w;
        float tt = v0.x*d0.x + v0.y*d0.y + v0.z*d0.z + v0.w*d0.w
                 + v1.x*d1.x + v1.y*d1.y + v1.z*d1.z + v1.w*d1.w;
        s  += __shfl_xor_sync(0xffffffffu, s, 1);
        tt += __shfl_xor_sync(0xffffffffu, tt, 1);
        s  += __shfl_xor_sync(0xffffffffu, s, 2);
        tt += __shfl_xor_sync(0xffffffffu, tt, 2);
        s  += __shfl_xor_sync(0xffffffffu, s, 4);
        tt += __shfl_xor_sync(0xffffffffu, tt, 4);
        if ((t & 7) == 0) {
            const int idx = h * NN + n0 + r;
            g_P[idx] = __expf(s);
            g_p[idx] = __expf(0.2f * s);
            g_Q[idx] = __expf(tt);
            g_q[idx] = __expf(0.2f * tt);
        }
    }
    __syncthreads();
    const int d  = t >> 2;
    const int ns = (t & 3) * 8;
    uint32_t o0[4], o1[4];
#pragma unroll
    for (int k = 0; k < 4; k++) {
        o0[k] = tf32r(tl[ns + k][d]);
        o1[k] = tf32r(tl[ns + 4 + k][d]);
    }
    size_t o = (size_t)(h * HD + d) * NN + n0 + ns;
    *(uint4*)(g_hTf + o)     = make_uint4(o0[0], o0[1], o0[2], o0[3]);
    *(uint4*)(g_hTf + o + 4) = make_uint4(o1[0], o1[1], o1[2], o1[3]);
}

// ---------------- Kernel 4: tf32 MMA masked softmax-aggregate ----------------
// CTA = 192 i x 1 head, 6 warps (192 thr), warp = 32 i x 64 d (two m16 frags
// sharing every B fragment load). grid (16, 8) = 128 CTAs -> single wave.
__global__ __launch_bounds__(192) void attn_kernel(float* __restrict__ out) {
    __shared__ __align__(16) float Bsm[2][HD * BROW];
    __shared__ __align__(8)  float2 QQ[2][KT];

    const int tid  = threadIdx.x;
    const int w    = tid >> 5;
    const int L    = tid & 31;
    const int head = blockIdx.y;
    const int i0   = blockIdx.x * MT;

    // staging role: tid < 128, thread = d-row (sd) x j-half (16 j's)
    const bool stager = tid < 128;
    const int sd   = tid >> 1;
    const int half = tid & 1;
    const float* hp = g_hTf + (size_t)(head * HD + (sd & 63)) * NN + half * 16;
    const int s0 = 4 * half;          // slot base for c4 = 2*half

    // fragment role: 4 i-rows per thread
    const int gr = L >> 2;
    const int c  = L & 3;
    const int ir0 = i0 + w * 32 + gr;
    const int ir1 = ir0 + 8;
    const int ir2 = ir0 + 16;
    const int ir3 = ir0 + 24;
    const float P0 = g_P[head * NN + ir0], p0 = g_p[head * NN + ir0];
    const float P1 = g_P[head * NN + ir1], p1 = g_p[head * NN + ir1];
    const float P2 = g_P[head * NN + ir2], p2 = g_p[head * NN + ir2];
    const float P3 = g_P[head * NN + ir3], p3 = g_p[head * NN + ir3];
    const unsigned* mr0 = g_mask + (size_t)ir0 * MW;
    const unsigned* mr1 = g_mask + (size_t)ir1 * MW;
    const unsigned* mr2 = g_mask + (size_t)ir2 * MW;
    const unsigned* mr3 = g_mask + (size_t)ir3 * MW;

    float acc[2][8][4];
#pragma unroll
    for (int mg = 0; mg < 2; mg++)
#pragma unroll
        for (int n = 0; n < 8; n++)
#pragma unroll
            for (int k = 0; k < 4; k++) acc[mg][n][k] = 0.f;
    float z0 = 0.f, z1 = 0.f, z2 = 0.f, z3 = 0.f;

    // prefetch tile 0
    float4 nv0, nv1, nv2, nv3;
    if (stager) {
        nv0 = *(const float4*)(hp + 0);
        nv1 = *(const float4*)(hp + 4);
        nv2 = *(const float4*)(hp + 8);
        nv3 = *(const float4*)(hp + 12);
    }
    unsigned nm0 = mr0[0], nm1 = mr1[0], nm2 = mr2[0], nm3 = mr3[0];
    float nQ = 0.f, nq = 0.f;
    if (tid < KT) {
        nQ = g_Q[head * NN + tid];
        nq = g_q[head * NN + tid];
    }

    for (int t = 0; t < NTILES; t++) {
        const int buf = t & 1;
        if (stager) {
            float* base = &Bsm[buf][sd * BROW];
            // c4 = 2*half: nv0 = j 16h+0..3 (m=0..3), nv1 = j 16h+4..7 (m=4..7)
            base[0 * 8 + s0]     = nv0.x;
            base[1 * 8 + s0]     = nv0.y;
            base[2 * 8 + s0]     = nv0.z;
            base[3 * 8 + s0]     = nv0.w;
            base[0 * 8 + s0 + 1] = nv1.x;
            base[1 * 8 + s0 + 1] = nv1.y;
            base[2 * 8 + s0 + 1] = nv1.z;
            base[3 * 8 + s0 + 1] = nv1.w;
            // c4 = 2*half+1: nv2 = j 16h+8..11, nv3 = j 16h+12..15
            base[0 * 8 + s0 + 2] = nv2.x;
            base[1 * 8 + s0 + 2] = nv2.y;
            base[2 * 8 + s0 + 2] = nv2.z;
            base[3 * 8 + s0 + 2] = nv2.w;
            base[0 * 8 + s0 + 3] = nv3.x;
            base[1 * 8 + s0 + 3] = nv3.y;
            base[2 * 8 + s0 + 3] = nv3.z;
            base[3 * 8 + s0 + 3] = nv3.w;
        }
        if (tid < KT) QQ[buf][tid] = make_float2(nQ, nq);
        const unsigned mw0 = nm0, mw1 = nm1, mw2 = nm2, mw3 = nm3;
        __syncthreads();

        if (t + 1 < NTILES) {
            const int j0 = (t + 1) * KT;
            if (stager) {
                nv0 = *(const float4*)(hp + j0 + 0);
                nv1 = *(const float4*)(hp + j0 + 4);
                nv2 = *(const float4*)(hp + j0 + 8);
                nv3 = *(const float4*)(hp + j0 + 12);
            }
            nm0 = mr0[t + 1]; nm1 = mr1[t + 1]; nm2 = mr2[t + 1]; nm3 = mr3[t + 1];
            if (tid < KT) {
                nQ = g_Q[head * NN + j0 + tid];
                nq = g_q[head * NN + j0 + tid];
            }
        }

        // A fragments for both m-tiles
        uint32_t A[2][4][4];
#pragma unroll
        for (int s = 0; s < 4; s++) {
            const int ja = 8 * s + c;
            const int jb = ja + 4;
            float2 qa = QQ[buf][ja];
            float2 qb = QQ[buf][jb];
            float wa0 = fmaxf(P0 * qa.x, p0 * qa.y); wa0 = ((mw0 >> ja) & 1u) ? wa0 : 0.f;
            float wa1 = fmaxf(P1 * qa.x, p1 * qa.y); wa1 = ((mw1 >> ja) & 1u) ? wa1 : 0.f;
            float wa2 = fmaxf(P2 * qa.x, p2 * qa.y); wa2 = ((mw2 >> ja) & 1u) ? wa2 : 0.f;
            float wa3 = fmaxf(P3 * qa.x, p3 * qa.y); wa3 = ((mw3 >> ja) & 1u) ? wa3 : 0.f;
            float wb0 = fmaxf(P0 * qb.x, p0 * qb.y); wb0 = ((mw0 >> jb) & 1u) ? wb0 : 0.f;
            float wb1 = fmaxf(P1 * qb.x, p1 * qb.y); wb1 = ((mw1 >> jb) & 1u) ? wb1 : 0.f;
            float wb2 = fmaxf(P2 * qb.x, p2 * qb.y); wb2 = ((mw2 >> jb) & 1u) ? wb2 : 0.f;
            float wb3 = fmaxf(P3 * qb.x, p3 * qb.y); wb3 = ((mw3 >> jb) & 1u) ? wb3 : 0.f;
            A[0][s][0] = tf32r(wa0);
            A[0][s][1] = tf32r(wa1);
            A[0][s][2] = tf32r(wb0);
            A[0][s][3] = tf32r(wb1);
            A[1][s][0] = tf32r(wa2);
            A[1][s][1] = tf32r(wa3);
            A[1][s][2] = tf32r(wb2);
            A[1][s][3] = tf32r(wb3);
            z0 += __uint_as_float(A[0][s][0]) + __uint_as_float(A[0][s][2]);
            z1 += __uint_as_float(A[0][s][1]) + __uint_as_float(A[0][s][3]);
            z2 += __uint_as_float(A[1][s][0]) + __uint_as_float(A[1][s][2]);
            z3 += __uint_as_float(A[1][s][1]) + __uint_as_float(A[1][s][3]);
        }

        // B loads shared by both m-tiles
#pragma unroll
        for (int nt = 0; nt < 8; nt++) {
            const float4* bp = (const float4*)(&Bsm[buf][(nt * 8 + gr) * BROW + c * 8]);
            float4 v0 = bp[0];
            float4 v1 = bp[1];
            mma_tf32(acc[0][nt], A[0][0], __float_as_uint(v0.x), __float_as_uint(v0.y));
            mma_tf32(acc[1][nt], A[1][0], __float_as_uint(v0.x), __float_as_uint(v0.y));
            mma_tf32(acc[0][nt], A[0][1], __float_as_uint(v0.z), __float_as_uint(v0.w));
            mma_tf32(acc[1][nt], A[1][1], __float_as_uint(v0.z), __float_as_uint(v0.w));
            mma_tf32(acc[0][nt], A[0][2], __float_as_uint(v1.x), __float_as_uint(v1.y));
            mma_tf32(acc[1][nt], A[1][2], __float_as_uint(v1.x), __float_as_uint(v1.y));
            mma_tf32(acc[0][nt], A[0][3], __float_as_uint(v1.z), __float_as_uint(v1.w));
            mma_tf32(acc[1][nt], A[1][3], __float_as_uint(v1.z), __float_as_uint(v1.w));
        }
        __syncthreads();
    }

    z0 += __shfl_xor_sync(0xffffffffu, z0, 1);
    z0 += __shfl_xor_sync(0xffffffffu, z0, 2);
    z1 += __shfl_xor_sync(0xffffffffu, z1, 1);
    z1 += __shfl_xor_sync(0xffffffffu, z1, 2);
    z2 += __shfl_xor_sync(0xffffffffu, z2, 1);
    z2 += __shfl_xor_sync(0xffffffffu, z2, 2);
    z3 += __shfl_xor_sync(0xffffffffu, z3, 1);
    z3 += __shfl_xor_sync(0xffffffffu, z3, 2);
    const float iz0 = 1.0f / z0;
    const float iz1 = 1.0f / z1;
    const float iz2 = 1.0f / z2;
    const float iz3 = 1.0f / z3;

    const int cb = c * 2;
    float* o0 = out + (size_t)ir0 * OF + head * HD + cb;
    float* o1 = out + (size_t)ir1 * OF + head * HD + cb;
    float* o2 = out + (size_t)ir2 * OF + head * HD + cb;
    float* o3 = out + (size_t)ir3 * OF + head * HD + cb;
#pragma unroll
    for (int nt = 0; nt < 8; nt++) {
        *(float2*)(o0 + nt * 8) = make_float2(acc[0][nt][0] * iz0, acc[0][nt][1] * iz0);
        *(float2*)(o1 + nt * 8) = make_float2(acc[0][nt][2] * iz1, acc[0][nt][3] * iz1);
        *(float2*)(o2 + nt * 8) = make_float2(acc[1][nt][0] * iz2, acc[1][nt][1] * iz2);
        *(float2*)(o3 + nt * 8) = make_float2(acc[1][nt][2] * iz3, acc[1][nt][3] * iz3);
    }
}

// ---------------- launch ----------------
extern "C" void kernel_launch(void* const* d_in, const int* in_sizes, int n_in,
                              void* d_out, int out_size) {
    const float* x     = (const float*)d_in[0];
    const int*   adj   = (const int*)d_in[1];
    const float* W     = (const float*)d_in[2];
    const float* a_src = (const float*)d_in[3];
    const float* a_dst = (const float*)d_in[4];
    float* out = (float*)d_out;

    __nv_bfloat16 *x1, *x2, *w1, *w2;
    cudaGetSymbolAddress((void**)&x1, g_X1);
    cudaGetSymbolAddress((void**)&x2, g_X2);
    cudaGetSymbolAddress((void**)&w1, g_W1);
    cudaGetSymbolAddress((void**)&w2, g_W2);

    fsplit_kernel<<<(NN * INF) / 1024, 256>>>(x, x1, x2);
    fsplit_kernel<<<(OF * INF) / 1024, 256>>>(W, w1, w2);
    mask_kernel<<<(NN * (NN / 256) * 32) / 256, 256>>>(adj);
    gemm_kernel<<<dim3(NN / 96, OF / 128), 384>>>();
    htrans_kernel<<<dim3(NN / 32, NH), 256>>>(a_src, a_dst);
    attn_kernel<<<dim3(NN / MT, NH), 192>>>(out);
}

// round 11
// speedup vs baseline: 1.3507x; 1.3507x over previous
#include <cuda_runtime.h>
#include <cuda_bf16.h>
#include <cuda_fp16.h>
#include <cstdint>

#define NN   3072
#define INF  512
#define NH   8
#define HD   64
#define OF   512   // NH*HD
#define MW   96    // mask words per row
#define KT   32    // attn j tile
#define MT   192   // attn i tile per CTA (12 warps x 16 i)
#define NTILES (NN / KT)

// ---------------- scratch ----------------
__device__ float         g_h[NN * OF];
__device__ float         g_P[NH * NN];
__device__ float         g_p[NH * NN];
__device__ float         g_Q[NH * NN];
__device__ float         g_q[NH * NN];
__device__ float         g_Qm[NH];
__device__ float         g_qm[NH];
__device__ unsigned      g_mask[NN * MW];
__device__ __half        g_hTh[NH * HD * NN];      // [h][d][n], fp16 h (transposed)
__device__ __nv_bfloat16 g_X1[NN * INF];
__device__ __nv_bfloat16 g_X2[NN * INF];
__device__ __nv_bfloat16 g_W1[OF * INF];
__device__ __nv_bfloat16 g_W2[OF * INF];

__device__ __forceinline__ uint32_t smem_u32(const void* p) {
    uint32_t a;
    asm("{ .reg .u64 t; cvta.to.shared.u64 t, %1; cvt.u32.u64 %0, t; }" : "=r"(a) : "l"(p));
    return a;
}

__device__ __forceinline__ void mma_bf16(float* c, const uint32_t* a, uint32_t b0, uint32_t b1) {
    asm volatile(
        "mma.sync.aligned.m16n8k16.row.col.f32.bf16.bf16.f32 "
        "{%0,%1,%2,%3}, {%4,%5,%6,%7}, {%8,%9}, {%0,%1,%2,%3};"
        : "+f"(c[0]), "+f"(c[1]), "+f"(c[2]), "+f"(c[3])
        : "r"(a[0]), "r"(a[1]), "r"(a[2]), "r"(a[3]), "r"(b0), "r"(b1));
}

__device__ __forceinline__ void mma_f16(float* c, const uint32_t* a, uint32_t b0, uint32_t b1) {
    asm volatile(
        "mma.sync.aligned.m16n8k16.row.col.f32.f16.f16.f32 "
        "{%0,%1,%2,%3}, {%4,%5,%6,%7}, {%8,%9}, {%0,%1,%2,%3};"
        : "+f"(c[0]), "+f"(c[1]), "+f"(c[2]), "+f"(c[3])
        : "r"(a[0]), "r"(a[1]), "r"(a[2]), "r"(a[3]), "r"(b0), "r"(b1));
}

__device__ __forceinline__ void ldmx4(uint32_t* r, uint32_t addr) {
    asm volatile("ldmatrix.sync.aligned.m8n8.x4.shared.b16 {%0,%1,%2,%3}, [%4];"
                 : "=r"(r[0]), "=r"(r[1]), "=r"(r[2]), "=r"(r[3]) : "r"(addr));
}

__device__ __forceinline__ void split2(float w0, float w1, uint32_t& hi, uint32_t& lo) {
    uint32_t h;
    asm("cvt.rn.bf16x2.f32 %0, %1, %2;" : "=r"(h) : "f"(w1), "f"(w0));
    float r0 = w0 - __uint_as_float(h << 16);
    float r1 = w1 - __uint_as_float(h & 0xffff0000u);
    uint32_t l;
    asm("cvt.rn.bf16x2.f32 %0, %1, %2;" : "=r"(l) : "f"(r1), "f"(r0));
    hi = h; lo = l;
}

// pack two fp32 -> fp16x2 (lo = a, hi = b)
__device__ __forceinline__ uint32_t packh2(float b, float a) {
    uint32_t r;
    asm("cvt.rn.f16x2.f32 %0, %1, %2;" : "=r"(r) : "f"(b), "f"(a));
    return r;
}

// ---------------- Kernel 0: fp32 -> bf16 hi/lo split ----------------
__global__ __launch_bounds__(256) void fsplit_kernel(const float* __restrict__ src,
                                                     __nv_bfloat16* __restrict__ dhi,
                                                     __nv_bfloat16* __restrict__ dlo) {
    const int idx = (blockIdx.x * blockDim.x + threadIdx.x) * 4;
    float4 v = *(const float4*)(src + idx);
    uint32_t h0, h1, l0, l1;
    split2(v.x, v.y, h0, l0);
    split2(v.z, v.w, h1, l1);
    *(uint2*)(dhi + idx) = make_uint2(h0, h1);
    *(uint2*)(dlo + idx) = make_uint2(l0, l1);
}

// ---------------- Kernel 1: g_h = X @ W^T (bf16-split HMMA) ----------------
// CTA = 96m x 128n, BK=32, grid (32, 4) = 128 CTAs -> single wave.
__global__ __launch_bounds__(384) void gemm_kernel() {
    __shared__ __align__(16) unsigned char Ah[2][96 * 64];
    __shared__ __align__(16) unsigned char Al[2][96 * 64];
    __shared__ __align__(16) unsigned char Bh[2][128 * 64];
    __shared__ __align__(16) unsigned char Bl[2][128 * 64];

    const int tid = threadIdx.x;
    const int w   = tid >> 5;
    const int L   = tid & 31;
    const int bm  = blockIdx.x * 96;
    const int bn  = blockIdx.y * 128;

    const int arow   = tid >> 2;
    const int achunk = tid & 3;
    const uint32_t aoff = (uint32_t)(arow * 64 + ((achunk ^ ((arow >> 1) & 3)) << 4));
    const int brow0  = tid >> 2;
    const int bchunk = tid & 3;
    const uint32_t boff0 = (uint32_t)(brow0 * 64 + ((bchunk ^ ((brow0 >> 1) & 3)) << 4));
    const int brow1  = 96 + (tid >> 2);
    const uint32_t boff1 = (uint32_t)(brow1 * 64 + ((bchunk ^ ((brow1 >> 1) & 3)) << 4));
    const bool hasB1 = tid < 128;

    const int warp_m = (w >> 2) * 32;
    const int warp_n = (w & 3) * 32;

    float acc[2][4][4];
#pragma unroll
    for (int mg = 0; mg < 2; mg++)
#pragma unroll
        for (int ng = 0; ng < 4; ng++)
#pragma unroll
            for (int k = 0; k < 4; k++) acc[mg][ng][k] = 0.f;

    uint4 xa_h, xa_l, wb_h0, wb_l0, wb_h1, wb_l1;
    {
        const size_t ao = (size_t)(bm + arow) * INF + achunk * 8;
        xa_h = *(const uint4*)(g_X1 + ao);
        xa_l = *(const uint4*)(g_X2 + ao);
        const size_t bo0 = (size_t)(bn + brow0) * INF + bchunk * 8;
        wb_h0 = *(const uint4*)(g_W1 + bo0);
        wb_l0 = *(const uint4*)(g_W2 + bo0);
        if (hasB1) {
            const size_t bo1 = (size_t)(bn + brow1) * INF + bchunk * 8;
            wb_h1 = *(const uint4*)(g_W1 + bo1);
            wb_l1 = *(const uint4*)(g_W2 + bo1);
        }
    }

    for (int it = 0; it < INF / 32; it++) {
        const int buf = it & 1;
        *(uint4*)&Ah[buf][aoff]  = xa_h;
        *(uint4*)&Al[buf][aoff]  = xa_l;
        *(uint4*)&Bh[buf][boff0] = wb_h0;
        *(uint4*)&Bl[buf][boff0] = wb_l0;
        if (hasB1) {
            *(uint4*)&Bh[buf][boff1] = wb_h1;
            *(uint4*)&Bl[buf][boff1] = wb_l1;
        }
        __syncthreads();

        if (it + 1 < INF / 32) {
            const int k0 = (it + 1) * 32;
            const size_t ao = (size_t)(bm + arow) * INF + k0 + achunk * 8;
            xa_h = *(const uint4*)(g_X1 + ao);
            xa_l = *(const uint4*)(g_X2 + ao);
            const size_t bo0 = (size_t)(bn + brow0) * INF + k0 + bchunk * 8;
            wb_h0 = *(const uint4*)(g_W1 + bo0);
            wb_l0 = *(const uint4*)(g_W2 + bo0);
            if (hasB1) {
                const size_t bo1 = (size_t)(bn + brow1) * INF + k0 + bchunk * 8;
                wb_h1 = *(const uint4*)(g_W1 + bo1);
                wb_l1 = *(const uint4*)(g_W2 + bo1);
            }
        }

        const uint32_t aAh = smem_u32(&Ah[buf][0]);
        const uint32_t aAl = smem_u32(&Al[buf][0]);
        const uint32_t aBh = smem_u32(&Bh[buf][0]);
        const uint32_t aBl = smem_u32(&Bl[buf][0]);

        uint32_t bh[4][4], bl[4][4];
#pragma unroll
        for (int ng = 0; ng < 4; ng++) {
            const int row = warp_n + ng * 8 + (L & 7);
            const int ch  = L >> 3;
            const uint32_t off = (uint32_t)(row * 64 + ((ch ^ ((row >> 1) & 3)) << 4));
            ldmx4(bh[ng], aBh + off);
            ldmx4(bl[ng], aBl + off);
        }
        uint32_t ah[2][2][4], al[2][2][4];
#pragma unroll
        for (int mg = 0; mg < 2; mg++)
#pragma unroll
            for (int ks = 0; ks < 2; ks++) {
                const int mat = L >> 3;
                const int row = warp_m + mg * 16 + (L & 7) + (mat & 1) * 8;
                const int ch  = ks * 2 + (mat >> 1);
                const uint32_t off = (uint32_t)(row * 64 + ((ch ^ ((row >> 1) & 3)) << 4));
                ldmx4(ah[mg][ks], aAh + off);
                ldmx4(al[mg][ks], aAl + off);
            }

#pragma unroll
        for (int mg = 0; mg < 2; mg++)
#pragma unroll
            for (int ng = 0; ng < 4; ng++)
#pragma unroll
                for (int ks = 0; ks < 2; ks++) {
                    mma_bf16(acc[mg][ng], ah[mg][ks], bh[ng][2*ks], bh[ng][2*ks+1]);
                    mma_bf16(acc[mg][ng], ah[mg][ks], bl[ng][2*ks], bl[ng][2*ks+1]);
                    mma_bf16(acc[mg][ng], al[mg][ks], bh[ng][2*ks], bh[ng][2*ks+1]);
                }
        __syncthreads();
    }

#pragma unroll
    for (int mg = 0; mg < 2; mg++)
#pragma unroll
        for (int ng = 0; ng < 4; ng++) {
            const int row = bm + warp_m + mg * 16 + (L >> 2);
            const int col = bn + warp_n + ng * 8 + (L & 3) * 2;
            *(float2*)(g_h + (size_t)row * OF + col)       = make_float2(acc[mg][ng][0], acc[mg][ng][1]);
            *(float2*)(g_h + (size_t)(row + 8) * OF + col) = make_float2(acc[mg][ng][2], acc[mg][ng][3]);
        }
}

// ---------------- Kernel 3: adjacency (+diag) bitmask, MLP=2 ----------------
__global__ __launch_bounds__(256) void mask_kernel(const int* __restrict__ adj) {
    const int gw = (blockIdx.x * blockDim.x + threadIdx.x) >> 5;
    const int L  = threadIdx.x & 31;
    const int i  = gw / (NN / 256);
    const int sp = gw % (NN / 256);
    const int c0 = sp * 256 + L * 4;
    const int c1 = c0 + 128;
    const int4 v0 = *(const int4*)(adj + (size_t)i * NN + c0);
    const int4 v1 = *(const int4*)(adj + (size_t)i * NN + c1);
    unsigned nib0 = ((v0.x != 0 || c0     == i) ? 1u : 0u)
                  | ((v0.y != 0 || c0 + 1 == i) ? 2u : 0u)
                  | ((v0.z != 0 || c0 + 2 == i) ? 4u : 0u)
                  | ((v0.w != 0 || c0 + 3 == i) ? 8u : 0u);
    unsigned nib1 = ((v1.x != 0 || c1     == i) ? 1u : 0u)
                  | ((v1.y != 0 || c1 + 1 == i) ? 2u : 0u)
                  | ((v1.z != 0 || c1 + 2 == i) ? 4u : 0u)
                  | ((v1.w != 0 || c1 + 3 == i) ? 8u : 0u);
    unsigned a = nib0 << ((L & 7) * 4);
    unsigned b = nib1 << ((L & 7) * 4);
    a |= __shfl_xor_sync(0xffffffffu, a, 1);
    b |= __shfl_xor_sync(0xffffffffu, b, 1);
    a |= __shfl_xor_sync(0xffffffffu, a, 2);
    b |= __shfl_xor_sync(0xffffffffu, b, 2);
    a |= __shfl_xor_sync(0xffffffffu, a, 4);
    b |= __shfl_xor_sync(0xffffffffu, b, 4);
    if ((L & 7) == 0) {
        g_mask[i * MW + sp * 8 + (L >> 3)]     = a;
        g_mask[i * MW + sp * 8 + 4 + (L >> 3)] = b;
    }
}

// ---------------- Kernel 3b: fused transpose(fp16) + coef ----------------
__global__ __launch_bounds__(256) void htrans_kernel(const float* __restrict__ a_src,
                                                     const float* __restrict__ a_dst) {
    __shared__ float tl[32][65];
    const int h  = blockIdx.y;
    const int n0 = blockIdx.x * 32;
    const int t  = threadIdx.x;
    const int r  = t >> 3;
    const int c8 = (t & 7) * 8;
    {
        const float* src = g_h + (size_t)(n0 + r) * OF + h * HD + c8;
        float4 v0 = *(const float4*)src;
        float4 v1 = *(const float4*)(src + 4);
        tl[r][c8+0] = v0.x; tl[r][c8+1] = v0.y; tl[r][c8+2] = v0.z; tl[r][c8+3] = v0.w;
        tl[r][c8+4] = v1.x; tl[r][c8+5] = v1.y; tl[r][c8+6] = v1.z; tl[r][c8+7] = v1.w;

        const float4* as = (const float4*)(a_src + h * HD + c8);
        const float4* ad = (const float4*)(a_dst + h * HD + c8);
        float4 a0 = as[0], a1 = as[1], d0 = ad[0], d1 = ad[1];
        float s = v0.x*a0.x + v0.y*a0.y + v0.z*a0.z + v0.w*a0.w
                + v1.x*a1.x + v1.y*a1.y + v1.z*a1.z + v1.w*a1.w;
        float tt = v0.x*d0.x + v0.y*d0.y + v0.z*d0.z + v0.w*d0.w
                 + v1.x*d1.x + v1.y*d1.y + v1.z*d1.z + v1.w*d1.w;
        s  += __shfl_xor_sync(0xffffffffu, s, 1);
        tt += __shfl_xor_sync(0xffffffffu, tt, 1);
        s  += __shfl_xor_sync(0xffffffffu, s, 2);
        tt += __shfl_xor_sync(0xffffffffu, tt, 2);
        s  += __shfl_xor_sync(0xffffffffu, s, 4);
        tt += __shfl_xor_sync(0xffffffffu, tt, 4);
        if ((t & 7) == 0) {
            const int idx = h * NN + n0 + r;
            g_P[idx] = __expf(s);
            g_p[idx] = __expf(0.2f * s);
            g_Q[idx] = __expf(tt);
            g_q[idx] = __expf(0.2f * tt);
        }
    }
    __syncthreads();
    const int d  = t >> 2;
    const int ns = (t & 3) * 8;
    uint32_t o0[4];
#pragma unroll
    for (int k = 0; k < 4; k++)
        o0[k] = packh2(tl[ns + 2*k + 1][d], tl[ns + 2*k][d]);
    *(uint4*)(g_hTh + (size_t)(h * HD + d) * NN + n0 + ns) = make_uint4(o0[0], o0[1], o0[2], o0[3]);
}

// ---------------- Kernel 3c: per-head max of Q, q ----------------
__global__ __launch_bounds__(256) void qred_kernel() {
    __shared__ float sm1[8], sm2[8];
    const int h = blockIdx.x;
    const int t = threadIdx.x;
    float m1 = 0.f, m2 = 0.f;
    for (int i = t; i < NN; i += 256) {
        m1 = fmaxf(m1, g_Q[h * NN + i]);
        m2 = fmaxf(m2, g_q[h * NN + i]);
    }
#pragma unroll
    for (int o = 16; o; o >>= 1) {
        m1 = fmaxf(m1, __shfl_xor_sync(0xffffffffu, m1, o));
        m2 = fmaxf(m2, __shfl_xor_sync(0xffffffffu, m2, o));
    }
    if ((t & 31) == 0) { sm1[t >> 5] = m1; sm2[t >> 5] = m2; }
    __syncthreads();
    if (t == 0) {
        float a = sm1[0], b = sm2[0];
#pragma unroll
        for (int k = 1; k < 8; k++) { a = fmaxf(a, sm1[k]); b = fmaxf(b, sm2[k]); }
        g_Qm[h] = a;
        g_qm[h] = b;
    }
}

// ---------------- Kernel 4: fp16 MMA masked softmax-aggregate ----------------
// CTA = 192 i x 1 head, 12 warps (384 thr), warp = 16 i x 64 d.
// w scaled per-row (w' <= 1, fp16-safe); Z computed by MMA vs ones-B from the
// SAME fp16 w' values -> exact cancellation; only h's 10-bit rounding remains.
// B smem: row d = 64B (32 fp16 j's), chunk swizzle: unit u -> chunk (u&3)^(d&3),
// pos u>>2. Consumer LDS.128 at chunk c^(d&3) yields all 4 B regs. grid 128 CTAs.
__global__ __launch_bounds__(384) void attn_kernel(float* __restrict__ out) {
    __shared__ __align__(16) unsigned char Bsm[2][HD * 64];   // 2 x 4KB
    __shared__ __align__(8)  float2 QQ[2][KT];

    const int tid  = threadIdx.x;
    const int w    = tid >> 5;
    const int L    = tid & 31;
    const int head = blockIdx.y;
    const int i0   = blockIdx.x * MT;

    // staging role: tid < 256: d row + 16B gmem chunk (4 b32 units)
    const bool stager = tid < 256;
    const int sd = (tid >> 2) & 63;
    const int q4 = tid & 3;
    const __half* hp = g_hTh + (size_t)(head * HD + sd) * NN;
    const int skey = sd & 3;

    // fragment role
    const int gr = L >> 2;
    const int c  = L & 3;
    const int irow0 = i0 + w * 16 + gr;
    const int irow1 = irow0 + 8;
    const float Qm = g_Qm[head];
    const float qm = g_qm[head];
    const float P0r = g_P[head * NN + irow0], p0r = g_p[head * NN + irow0];
    const float P1r = g_P[head * NN + irow1], p1r = g_p[head * NN + irow1];
    const float s0 = 1.0f / (P0r * Qm + p0r * qm);
    const float s1 = 1.0f / (P1r * Qm + p1r * qm);
    const float P0 = P0r * s0, p0 = p0r * s0;
    const float P1 = P1r * s1, p1 = p1r * s1;
    const unsigned* mrow0 = g_mask + (size_t)irow0 * MW;
    const unsigned* mrow1 = g_mask + (size_t)irow1 * MW;

    const uint32_t ONE2 = 0x3C003C00u;   // fp16 {1.0, 1.0}

    float acc[8][4];
#pragma unroll
    for (int n = 0; n < 8; n++)
#pragma unroll
        for (int k = 0; k < 4; k++) acc[n][k] = 0.f;
    float zacc[4] = {0.f, 0.f, 0.f, 0.f};

    // prefetch tile 0
    uint4 nv;
    if (stager) nv = *(const uint4*)(hp + q4 * 8);
    unsigned nm0 = mrow0[0];
    unsigned nm1 = mrow1[0];
    float nQ = 0.f, nq = 0.f;
    if (tid < KT) {
        nQ = g_Q[head * NN + tid];
        nq = g_q[head * NN + tid];
    }

    for (int t = 0; t < NTILES; t++) {
        const int buf = t & 1;
        if (stager) {
            unsigned char* base = &Bsm[buf][sd * 64];
            const int ppos = q4 * 4;
            *(uint32_t*)(base + (((0 ^ skey) << 4) + ppos)) = nv.x;
            *(uint32_t*)(base + (((1 ^ skey) << 4) + ppos)) = nv.y;
            *(uint32_t*)(base + (((2 ^ skey) << 4) + ppos)) = nv.z;
            *(uint32_t*)(base + (((3 ^ skey) << 4) + ppos)) = nv.w;
        }
        if (tid < KT) QQ[buf][tid] = make_float2(nQ, nq);
        const unsigned mw0 = nm0;
        const unsigned mw1 = nm1;
        __syncthreads();

        if (t + 1 < NTILES) {
            const int j0 = (t + 1) * KT;
            if (stager) nv = *(const uint4*)(hp + j0 + q4 * 8);
            nm0 = mrow0[t + 1];
            nm1 = mrow1[t + 1];
            if (tid < KT) {
                nQ = g_Q[head * NN + j0 + tid];
                nq = g_q[head * NN + j0 + tid];
            }
        }

        // ---- A fragments (fp16 w', masked, per-row scaled) ----
        uint32_t A[2][4];
#pragma unroll
        for (int s = 0; s < 2; s++) {
            const int ja = 16 * s + 2 * c;
            float2 qa0 = QQ[buf][ja];
            float2 qa1 = QQ[buf][ja + 1];
            float2 qb0 = QQ[buf][ja + 8];
            float2 qb1 = QQ[buf][ja + 9];
            float w00 = fmaxf(P0 * qa0.x, p0 * qa0.y); w00 = ((mw0 >> ja)       & 1u) ? w00 : 0.f;
            float w01 = fmaxf(P0 * qa1.x, p0 * qa1.y); w01 = ((mw0 >> (ja + 1)) & 1u) ? w01 : 0.f;
            float w02 = fmaxf(P0 * qb0.x, p0 * qb0.y); w02 = ((mw0 >> (ja + 8)) & 1u) ? w02 : 0.f;
            float w03 = fmaxf(P0 * qb1.x, p0 * qb1.y); w03 = ((mw0 >> (ja + 9)) & 1u) ? w03 : 0.f;
            float w10 = fmaxf(P1 * qa0.x, p1 * qa0.y); w10 = ((mw1 >> ja)       & 1u) ? w10 : 0.f;
            float w11 = fmaxf(P1 * qa1.x, p1 * qa1.y); w11 = ((mw1 >> (ja + 1)) & 1u) ? w11 : 0.f;
            float w12 = fmaxf(P1 * qb0.x, p1 * qb0.y); w12 = ((mw1 >> (ja + 8)) & 1u) ? w12 : 0.f;
            float w13 = fmaxf(P1 * qb1.x, p1 * qb1.y); w13 = ((mw1 >> (ja + 9)) & 1u) ? w13 : 0.f;
            A[s][0] = packh2(w01, w00);
            A[s][1] = packh2(w11, w10);
            A[s][2] = packh2(w03, w02);
            A[s][3] = packh2(w13, w12);
        }

        // ---- B fragment loads (one LDS.128 per nt) + MMA ----
#pragma unroll
        for (int nt = 0; nt < 8; nt++) {
            const int d = nt * 8 + gr;
            uint4 v = *(const uint4*)(&Bsm[buf][d * 64 + ((c ^ (gr & 3)) << 4)]);
            mma_f16(acc[nt], A[0], v.x, v.y);
            mma_f16(acc[nt], A[1], v.z, v.w);
        }
        // Z via ones-B MMA (same fp16 w' values -> exact weight cancellation)
        mma_f16(zacc, A[0], ONE2, ONE2);
        mma_f16(zacc, A[1], ONE2, ONE2);
        __syncthreads();
    }

    const float iz0 = 1.0f / zacc[0];   // row irow0 sum (all cols equal)
    const float iz1 = 1.0f / zacc[2];   // row irow1 sum

    const int cb = c * 2;
    float* o0 = out + (size_t)irow0 * OF + head * HD + cb;
    float* o1 = out + (size_t)irow1 * OF + head * HD + cb;
#pragma unroll
    for (int nt = 0; nt < 8; nt++) {
        *(float2*)(o0 + nt * 8) = make_float2(acc[nt][0] * iz0, acc[nt][1] * iz0);
        *(float2*)(o1 + nt * 8) = make_float2(acc[nt][2] * iz1, acc[nt][3] * iz1);
    }
}

// ---------------- launch ----------------
extern "C" void kernel_launch(void* const* d_in, const int* in_sizes, int n_in,
                              void* d_out, int out_size) {
    const float* x     = (const float*)d_in[0];
    const int*   adj   = (const int*)d_in[1];
    const float* W     = (const float*)d_in[2];
    const float* a_src = (const float*)d_in[3];
    const float* a_dst = (const float*)d_in[4];
    float* out = (float*)d_out;

    __nv_bfloat16 *x1, *x2, *w1, *w2;
    cudaGetSymbolAddress((void**)&x1, g_X1);
    cudaGetSymbolAddress((void**)&x2, g_X2);
    cudaGetSymbolAddress((void**)&w1, g_W1);
    cudaGetSymbolAddress((void**)&w2, g_W2);

    fsplit_kernel<<<(NN * INF) / 1024, 256>>>(x, x1, x2);
    fsplit_kernel<<<(OF * INF) / 1024, 256>>>(W, w1, w2);
    mask_kernel<<<(NN * (NN / 256) * 32) / 256, 256>>>(adj);
    gemm_kernel<<<dim3(NN / 96, OF / 128), 384>>>();
    htrans_kernel<<<dim3(NN / 32, NH), 256>>>(a_src, a_dst);
    qred_kernel<<<NH, 256>>>();
    attn_kernel<<<dim3(NN / MT, NH), 384>>>(out);
}

// round 12
// speedup vs baseline: 1.4020x; 1.0380x over previous
#include <cuda_runtime.h>
#include <cuda_bf16.h>
#include <cuda_fp16.h>
#include <cstdint>

#define NN   3072
#define INF  512
#define NH   8
#define HD   64
#define OF   512   // NH*HD
#define MW   96    // mask words per row
#define KT2  64    // attn j double-tile (two 32-j half-tiles per sync)
#define MT   192   // attn i tile per CTA (12 warps x 16 i)
#define NT2  (NN / KT2)

// ---------------- scratch ----------------
__device__ float         g_h[NN * OF];
__device__ float         g_P[NH * NN];
__device__ float         g_p[NH * NN];
__device__ float         g_Q[NH * NN];
__device__ float         g_q[NH * NN];
__device__ float         g_Qm[NH];
__device__ float         g_qm[NH];
__device__ unsigned      g_mask[NN * MW];
__device__ __half        g_hTh[NH * HD * NN];      // [h][d][n], fp16 h (transposed)
__device__ __nv_bfloat16 g_X1[NN * INF];
__device__ __nv_bfloat16 g_X2[NN * INF];
__device__ __nv_bfloat16 g_W1[OF * INF];
__device__ __nv_bfloat16 g_W2[OF * INF];

__device__ __forceinline__ uint32_t smem_u32(const void* p) {
    uint32_t a;
    asm("{ .reg .u64 t; cvta.to.shared.u64 t, %1; cvt.u32.u64 %0, t; }" : "=r"(a) : "l"(p));
    return a;
}

__device__ __forceinline__ void mma_bf16(float* c, const uint32_t* a, uint32_t b0, uint32_t b1) {
    asm volatile(
        "mma.sync.aligned.m16n8k16.row.col.f32.bf16.bf16.f32 "
        "{%0,%1,%2,%3}, {%4,%5,%6,%7}, {%8,%9}, {%0,%1,%2,%3};"
        : "+f"(c[0]), "+f"(c[1]), "+f"(c[2]), "+f"(c[3])
        : "r"(a[0]), "r"(a[1]), "r"(a[2]), "r"(a[3]), "r"(b0), "r"(b1));
}

__device__ __forceinline__ void mma_f16(float* c, const uint32_t* a, uint32_t b0, uint32_t b1) {
    asm volatile(
        "mma.sync.aligned.m16n8k16.row.col.f32.f16.f16.f32 "
        "{%0,%1,%2,%3}, {%4,%5,%6,%7}, {%8,%9}, {%0,%1,%2,%3};"
        : "+f"(c[0]), "+f"(c[1]), "+f"(c[2]), "+f"(c[3])
        : "r"(a[0]), "r"(a[1]), "r"(a[2]), "r"(a[3]), "r"(b0), "r"(b1));
}

__device__ __forceinline__ void ldmx4(uint32_t* r, uint32_t addr) {
    asm volatile("ldmatrix.sync.aligned.m8n8.x4.shared.b16 {%0,%1,%2,%3}, [%4];"
                 : "=r"(r[0]), "=r"(r[1]), "=r"(r[2]), "=r"(r[3]) : "r"(addr));
}

__device__ __forceinline__ void split2(float w0, float w1, uint32_t& hi, uint32_t& lo) {
    uint32_t h;
    asm("cvt.rn.bf16x2.f32 %0, %1, %2;" : "=r"(h) : "f"(w1), "f"(w0));
    float r0 = w0 - __uint_as_float(h << 16);
    float r1 = w1 - __uint_as_float(h & 0xffff0000u);
    uint32_t l;
    asm("cvt.rn.bf16x2.f32 %0, %1, %2;" : "=r"(l) : "f"(r1), "f"(r0));
    hi = h; lo = l;
}

// pack two fp32 -> fp16x2 (lo = a, hi = b)
__device__ __forceinline__ uint32_t packh2(float b, float a) {
    uint32_t r;
    asm("cvt.rn.f16x2.f32 %0, %1, %2;" : "=r"(r) : "f"(b), "f"(a));
    return r;
}

// ---------------- Kernel 0: fp32 -> bf16 hi/lo split ----------------
__global__ __launch_bounds__(256) void fsplit_kernel(const float* __restrict__ src,
                                                     __nv_bfloat16* __restrict__ dhi,
                                                     __nv_bfloat16* __restrict__ dlo) {
    const int idx = (blockIdx.x * blockDim.x + threadIdx.x) * 4;
    float4 v = *(const float4*)(src + idx);
    uint32_t h0, h1, l0, l1;
    split2(v.x, v.y, h0, l0);
    split2(v.z, v.w, h1, l1);
    *(uint2*)(dhi + idx) = make_uint2(h0, h1);
    *(uint2*)(dlo + idx) = make_uint2(l0, l1);
}

// ---------------- Kernel 1: g_h = X @ W^T (bf16-split HMMA) ----------------
// CTA = 96m x 128n, BK=32, grid (32, 4) = 128 CTAs -> single wave.
__global__ __launch_bounds__(384) void gemm_kernel() {
    __shared__ __align__(16) unsigned char Ah[2][96 * 64];
    __shared__ __align__(16) unsigned char Al[2][96 * 64];
    __shared__ __align__(16) unsigned char Bh[2][128 * 64];
    __shared__ __align__(16) unsigned char Bl[2][128 * 64];

    const int tid = threadIdx.x;
    const int w   = tid >> 5;
    const int L   = tid & 31;
    const int bm  = blockIdx.x * 96;
    const int bn  = blockIdx.y * 128;

    const int arow   = tid >> 2;
    const int achunk = tid & 3;
    const uint32_t aoff = (uint32_t)(arow * 64 + ((achunk ^ ((arow >> 1) & 3)) << 4));
    const int brow0  = tid >> 2;
    const int bchunk = tid & 3;
    const uint32_t boff0 = (uint32_t)(brow0 * 64 + ((bchunk ^ ((brow0 >> 1) & 3)) << 4));
    const int brow1  = 96 + (tid >> 2);
    const uint32_t boff1 = (uint32_t)(brow1 * 64 + ((bchunk ^ ((brow1 >> 1) & 3)) << 4));
    const bool hasB1 = tid < 128;

    const int warp_m = (w >> 2) * 32;
    const int warp_n = (w & 3) * 32;

    float acc[2][4][4];
#pragma unroll
    for (int mg = 0; mg < 2; mg++)
#pragma unroll
        for (int ng = 0; ng < 4; ng++)
#pragma unroll
            for (int k = 0; k < 4; k++) acc[mg][ng][k] = 0.f;

    uint4 xa_h, xa_l, wb_h0, wb_l0, wb_h1, wb_l1;
    {
        const size_t ao = (size_t)(bm + arow) * INF + achunk * 8;
        xa_h = *(const uint4*)(g_X1 + ao);
        xa_l = *(const uint4*)(g_X2 + ao);
        const size_t bo0 = (size_t)(bn + brow0) * INF + bchunk * 8;
        wb_h0 = *(const uint4*)(g_W1 + bo0);
        wb_l0 = *(const uint4*)(g_W2 + bo0);
        if (hasB1) {
            const size_t bo1 = (size_t)(bn + brow1) * INF + bchunk * 8;
            wb_h1 = *(const uint4*)(g_W1 + bo1);
            wb_l1 = *(const uint4*)(g_W2 + bo1);
        }
    }

    for (int it = 0; it < INF / 32; it++) {
        const int buf = it & 1;
        *(uint4*)&Ah[buf][aoff]  = xa_h;
        *(uint4*)&Al[buf][aoff]  = xa_l;
        *(uint4*)&Bh[buf][boff0] = wb_h0;
        *(uint4*)&Bl[buf][boff0] = wb_l0;
        if (hasB1) {
            *(uint4*)&Bh[buf][boff1] = wb_h1;
            *(uint4*)&Bl[buf][boff1] = wb_l1;
        }
        __syncthreads();

        if (it + 1 < INF / 32) {
            const int k0 = (it + 1) * 32;
            const size_t ao = (size_t)(bm + arow) * INF + k0 + achunk * 8;
            xa_h = *(const uint4*)(g_X1 + ao);
            xa_l = *(const uint4*)(g_X2 + ao);
            const size_t bo0 = (size_t)(bn + brow0) * INF + k0 + bchunk * 8;
            wb_h0 = *(const uint4*)(g_W1 + bo0);
            wb_l0 = *(const uint4*)(g_W2 + bo0);
            if (hasB1) {
                const size_t bo1 = (size_t)(bn + brow1) * INF + k0 + bchunk * 8;
                wb_h1 = *(const uint4*)(g_W1 + bo1);
                wb_l1 = *(const uint4*)(g_W2 + bo1);
            }
        }

        const uint32_t aAh = smem_u32(&Ah[buf][0]);
        const uint32_t aAl = smem_u32(&Al[buf][0]);
        const uint32_t aBh = smem_u32(&Bh[buf][0]);
        const uint32_t aBl = smem_u32(&Bl[buf][0]);

        uint32_t bh[4][4], bl[4][4];
#pragma unroll
        for (int ng = 0; ng < 4; ng++) {
            const int row = warp_n + ng * 8 + (L & 7);
            const int ch  = L >> 3;
            const uint32_t off = (uint32_t)(row * 64 + ((ch ^ ((row >> 1) & 3)) << 4));
            ldmx4(bh[ng], aBh + off);
            ldmx4(bl[ng], aBl + off);
        }
        uint32_t ah[2][2][4], al[2][2][4];
#pragma unroll
        for (int mg = 0; mg < 2; mg++)
#pragma unroll
            for (int ks = 0; ks < 2; ks++) {
                const int mat = L >> 3;
                const int row = warp_m + mg * 16 + (L & 7) + (mat & 1) * 8;
                const int ch  = ks * 2 + (mat >> 1);
                const uint32_t off = (uint32_t)(row * 64 + ((ch ^ ((row >> 1) & 3)) << 4));
                ldmx4(ah[mg][ks], aAh + off);
                ldmx4(al[mg][ks], aAl + off);
            }

#pragma unroll
        for (int mg = 0; mg < 2; mg++)
#pragma unroll
            for (int ng = 0; ng < 4; ng++)
#pragma unroll
                for (int ks = 0; ks < 2; ks++) {
                    mma_bf16(acc[mg][ng], ah[mg][ks], bh[ng][2*ks], bh[ng][2*ks+1]);
                    mma_bf16(acc[mg][ng], ah[mg][ks], bl[ng][2*ks], bl[ng][2*ks+1]);
                    mma_bf16(acc[mg][ng], al[mg][ks], bh[ng][2*ks], bh[ng][2*ks+1]);
                }
        __syncthreads();
    }

#pragma unroll
    for (int mg = 0; mg < 2; mg++)
#pragma unroll
        for (int ng = 0; ng < 4; ng++) {
            const int row = bm + warp_m + mg * 16 + (L >> 2);
            const int col = bn + warp_n + ng * 8 + (L & 3) * 2;
            *(float2*)(g_h + (size_t)row * OF + col)       = make_float2(acc[mg][ng][0], acc[mg][ng][1]);
            *(float2*)(g_h + (size_t)(row + 8) * OF + col) = make_float2(acc[mg][ng][2], acc[mg][ng][3]);
        }
}

// ---------------- Kernel 3: adjacency (+diag) bitmask, MLP=2 ----------------
__global__ __launch_bounds__(256) void mask_kernel(const int* __restrict__ adj) {
    const int gw = (blockIdx.x * blockDim.x + threadIdx.x) >> 5;
    const int L  = threadIdx.x & 31;
    const int i  = gw / (NN / 256);
    const int sp = gw % (NN / 256);
    const int c0 = sp * 256 + L * 4;
    const int c1 = c0 + 128;
    const int4 v0 = *(const int4*)(adj + (size_t)i * NN + c0);
    const int4 v1 = *(const int4*)(adj + (size_t)i * NN + c1);
    unsigned nib0 = ((v0.x != 0 || c0     == i) ? 1u : 0u)
                  | ((v0.y != 0 || c0 + 1 == i) ? 2u : 0u)
                  | ((v0.z != 0 || c0 + 2 == i) ? 4u : 0u)
                  | ((v0.w != 0 || c0 + 3 == i) ? 8u : 0u);
    unsigned nib1 = ((v1.x != 0 || c1     == i) ? 1u : 0u)
                  | ((v1.y != 0 || c1 + 1 == i) ? 2u : 0u)
                  | ((v1.z != 0 || c1 + 2 == i) ? 4u : 0u)
                  | ((v1.w != 0 || c1 + 3 == i) ? 8u : 0u);
    unsigned a = nib0 << ((L & 7) * 4);
    unsigned b = nib1 << ((L & 7) * 4);
    a |= __shfl_xor_sync(0xffffffffu, a, 1);
    b |= __shfl_xor_sync(0xffffffffu, b, 1);
    a |= __shfl_xor_sync(0xffffffffu, a, 2);
    b |= __shfl_xor_sync(0xffffffffu, b, 2);
    a |= __shfl_xor_sync(0xffffffffu, a, 4);
    b |= __shfl_xor_sync(0xffffffffu, b, 4);
    if ((L & 7) == 0) {
        g_mask[i * MW + sp * 8 + (L >> 3)]     = a;
        g_mask[i * MW + sp * 8 + 4 + (L >> 3)] = b;
    }
}

// ---------------- Kernel 3b: fused transpose(fp16) + coef ----------------
__global__ __launch_bounds__(256) void htrans_kernel(const float* __restrict__ a_src,
                                                     const float* __restrict__ a_dst) {
    __shared__ float tl[32][65];
    const int h  = blockIdx.y;
    const int n0 = blockIdx.x * 32;
    const int t  = threadIdx.x;
    const int r  = t >> 3;
    const int c8 = (t & 7) * 8;
    {
        const float* src = g_h + (size_t)(n0 + r) * OF + h * HD + c8;
        float4 v0 = *(const float4*)src;
        float4 v1 = *(const float4*)(src + 4);
        tl[r][c8+0] = v0.x; tl[r][c8+1] = v0.y; tl[r][c8+2] = v0.z; tl[r][c8+3] = v0.w;
        tl[r][c8+4] = v1.x; tl[r][c8+5] = v1.y; tl[r][c8+6] = v1.z; tl[r][c8+7] = v1.w;

        const float4* as = (const float4*)(a_src + h * HD + c8);
        const float4* ad = (const float4*)(a_dst + h * HD + c8);
        float4 a0 = as[0], a1 = as[1], d0 = ad[0], d1 = ad[1];
        float s = v0.x*a0.x + v0.y*a0.y + v0.z*a0.z + v0.w*a0.w
                + v1.x*a1.x + v1.y*a1.y + v1.z*a1.z + v1.w*a1.w;
        float tt = v0.x*d0.x + v0.y*d0.y + v0.z*d0.z + v0.w*d0.w
                 + v1.x*d1.x + v1.y*d1.y + v1.z*d1.z + v1.w*d1.w;
        s  += __shfl_xor_sync(0xffffffffu, s, 1);
        tt += __shfl_xor_sync(0xffffffffu, tt, 1);
        s  += __shfl_xor_sync(0xffffffffu, s, 2);
        tt += __shfl_xor_sync(0xffffffffu, tt, 2);
        s  += __shfl_xor_sync(0xffffffffu, s, 4);
        tt += __shfl_xor_sync(0xffffffffu, tt, 4);
        if ((t & 7) == 0) {
            const int idx = h * NN + n0 + r;
            g_P[idx] = __expf(s);
            g_p[idx] = __expf(0.2f * s);
            g_Q[idx] = __expf(tt);
            g_q[idx] = __expf(0.2f * tt);
        }
    }
    __syncthreads();
    const int d  = t >> 2;
    const int ns = (t & 3) * 8;
    uint32_t o0[4];
#pragma unroll
    for (int k = 0; k < 4; k++)
        o0[k] = packh2(tl[ns + 2*k + 1][d], tl[ns + 2*k][d]);
    *(uint4*)(g_hTh + (size_t)(h * HD + d) * NN + n0 + ns) = make_uint4(o0[0], o0[1], o0[2], o0[3]);
}

// ---------------- Kernel 3c: per-head max of Q, q ----------------
__global__ __launch_bounds__(256) void qred_kernel() {
    __shared__ float sm1[8], sm2[8];
    const int h = blockIdx.x;
    const int t = threadIdx.x;
    float m1 = 0.f, m2 = 0.f;
    for (int i = t; i < NN; i += 256) {
        m1 = fmaxf(m1, g_Q[h * NN + i]);
        m2 = fmaxf(m2, g_q[h * NN + i]);
    }
#pragma unroll
    for (int o = 16; o; o >>= 1) {
        m1 = fmaxf(m1, __shfl_xor_sync(0xffffffffu, m1, o));
        m2 = fmaxf(m2, __shfl_xor_sync(0xffffffffu, m2, o));
    }
    if ((t & 31) == 0) { sm1[t >> 5] = m1; sm2[t >> 5] = m2; }
    __syncthreads();
    if (t == 0) {
        float a = sm1[0], b = sm2[0];
#pragma unroll
        for (int k = 1; k < 8; k++) { a = fmaxf(a, sm1[k]); b = fmaxf(b, sm2[k]); }
        g_Qm[h] = a;
        g_qm[h] = b;
    }
}

// ---------------- Kernel 4: fp16 MMA masked softmax-aggregate, KT=64 ----------------
// CTA = 192 i x 1 head, 12 warps. Per sync: TWO independent 32-j half-tiles, each
// using the proven conflict-free layout. Halves barrier count (48 iters).
__global__ __launch_bounds__(384) void attn_kernel(float* __restrict__ out) {
    __shared__ __align__(16) unsigned char Bsm[2][2][HD * 64];  // [buf][half] 4KB each
    __shared__ __align__(8)  float2 QQ[2][KT2];

    const int tid  = threadIdx.x;
    const int w    = tid >> 5;
    const int L    = tid & 31;
    const int head = blockIdx.y;
    const int i0   = blockIdx.x * MT;

    // staging role: tid < 256: d row + 16B gmem chunk, both halves
    const bool stager = tid < 256;
    const int sd = (tid >> 2) & 63;
    const int q4 = tid & 3;
    const __half* hp = g_hTh + (size_t)(head * HD + sd) * NN;
    const int skey = sd & 3;
    const int ppos = q4 * 4;

    // fragment role
    const int gr = L >> 2;
    const int c  = L & 3;
    const int irow0 = i0 + w * 16 + gr;
    const int irow1 = irow0 + 8;
    const float Qm = g_Qm[head];
    const float qm = g_qm[head];
    const float P0r = g_P[head * NN + irow0], p0r = g_p[head * NN + irow0];
    const float P1r = g_P[head * NN + irow1], p1r = g_p[head * NN + irow1];
    const float sc0 = 1.0f / (P0r * Qm + p0r * qm);
    const float sc1 = 1.0f / (P1r * Qm + p1r * qm);
    const float P0 = P0r * sc0, p0 = p0r * sc0;
    const float P1 = P1r * sc1, p1 = p1r * sc1;
    const unsigned* mrow0 = g_mask + (size_t)irow0 * MW;
    const unsigned* mrow1 = g_mask + (size_t)irow1 * MW;

    const uint32_t ONE2 = 0x3C003C00u;   // fp16 {1.0, 1.0}

    float acc[8][4];
#pragma unroll
    for (int n = 0; n < 8; n++)
#pragma unroll
        for (int k = 0; k < 4; k++) acc[n][k] = 0.f;
    float zacc[4] = {0.f, 0.f, 0.f, 0.f};

    // prefetch tile 0
    uint4 nva, nvb;
    if (stager) {
        nva = *(const uint4*)(hp + q4 * 8);
        nvb = *(const uint4*)(hp + 32 + q4 * 8);
    }
    unsigned nm0a = mrow0[0], nm0b = mrow0[1];
    unsigned nm1a = mrow1[0], nm1b = mrow1[1];
    float nQ = 0.f, nq = 0.f;
    if (tid < KT2) {
        nQ = g_Q[head * NN + tid];
        nq = g_q[head * NN + tid];
    }

    for (int t = 0; t < NT2; t++) {
        const int buf = t & 1;
        if (stager) {
            unsigned char* ba = &Bsm[buf][0][sd * 64];
            unsigned char* bb = &Bsm[buf][1][sd * 64];
            *(uint32_t*)(ba + (((0 ^ skey) << 4) + ppos)) = nva.x;
            *(uint32_t*)(ba + (((1 ^ skey) << 4) + ppos)) = nva.y;
            *(uint32_t*)(ba + (((2 ^ skey) << 4) + ppos)) = nva.z;
            *(uint32_t*)(ba + (((3 ^ skey) << 4) + ppos)) = nva.w;
            *(uint32_t*)(bb + (((0 ^ skey) << 4) + ppos)) = nvb.x;
            *(uint32_t*)(bb + (((1 ^ skey) << 4) + ppos)) = nvb.y;
            *(uint32_t*)(bb + (((2 ^ skey) << 4) + ppos)) = nvb.z;
            *(uint32_t*)(bb + (((3 ^ skey) << 4) + ppos)) = nvb.w;
        }
        if (tid < KT2) QQ[buf][tid] = make_float2(nQ, nq);
        const unsigned mw0a = nm0a, mw0b = nm0b;
        const unsigned mw1a = nm1a, mw1b = nm1b;
        __syncthreads();

        if (t + 1 < NT2) {
            const int j0 = (t + 1) * KT2;
            if (stager) {
                nva = *(const uint4*)(hp + j0 + q4 * 8);
                nvb = *(const uint4*)(hp + j0 + 32 + q4 * 8);
            }
            nm0a = mrow0[2 * (t + 1)];
            nm0b = mrow0[2 * (t + 1) + 1];
            nm1a = mrow1[2 * (t + 1)];
            nm1b = mrow1[2 * (t + 1) + 1];
            if (tid < KT2) {
                nQ = g_Q[head * NN + j0 + tid];
                nq = g_q[head * NN + j0 + tid];
            }
        }

        // ---- A fragments for both halves ----
        uint32_t A0[2][4], A1[2][4];
#pragma unroll
        for (int hf = 0; hf < 2; hf++) {
            const unsigned m0 = hf ? mw0b : mw0a;
            const unsigned m1 = hf ? mw1b : mw1a;
            uint32_t (*A)[4] = hf ? A1 : A0;
#pragma unroll
            for (int s = 0; s < 2; s++) {
                const int ja = 16 * s + 2 * c;
                const int jq = hf * 32 + ja;
                float2 qa0 = QQ[buf][jq];
                float2 qa1 = QQ[buf][jq + 1];
                float2 qb0 = QQ[buf][jq + 8];
                float2 qb1 = QQ[buf][jq + 9];
                float w00 = fmaxf(P0 * qa0.x, p0 * qa0.y); w00 = ((m0 >> ja)       & 1u) ? w00 : 0.f;
                float w01 = fmaxf(P0 * qa1.x, p0 * qa1.y); w01 = ((m0 >> (ja + 1)) & 1u) ? w01 : 0.f;
                float w02 = fmaxf(P0 * qb0.x, p0 * qb0.y); w02 = ((m0 >> (ja + 8)) & 1u) ? w02 : 0.f;
                float w03 = fmaxf(P0 * qb1.x, p0 * qb1.y); w03 = ((m0 >> (ja + 9)) & 1u) ? w03 : 0.f;
                float w10 = fmaxf(P1 * qa0.x, p1 * qa0.y); w10 = ((m1 >> ja)       & 1u) ? w10 : 0.f;
                float w11 = fmaxf(P1 * qa1.x, p1 * qa1.y); w11 = ((m1 >> (ja + 1)) & 1u) ? w11 : 0.f;
                float w12 = fmaxf(P1 * qb0.x, p1 * qb0.y); w12 = ((m1 >> (ja + 8)) & 1u) ? w12 : 0.f;
                float w13 = fmaxf(P1 * qb1.x, p1 * qb1.y); w13 = ((m1 >> (ja + 9)) & 1u) ? w13 : 0.f;
                A[s][0] = packh2(w01, w00);
                A[s][1] = packh2(w11, w10);
                A[s][2] = packh2(w03, w02);
                A[s][3] = packh2(w13, w12);
            }
        }

        // ---- B fragment loads + MMA, both halves ----
#pragma unroll
        for (int nt = 0; nt < 8; nt++) {
            const int d = nt * 8 + gr;
            const uint32_t off = (uint32_t)(d * 64 + ((c ^ (gr & 3)) << 4));
            uint4 va = *(const uint4*)(&Bsm[buf][0][off]);
            uint4 vb = *(const uint4*)(&Bsm[buf][1][off]);
            mma_f16(acc[nt], A0[0], va.x, va.y);
            mma_f16(acc[nt], A0[1], va.z, va.w);
            mma_f16(acc[nt], A1[0], vb.x, vb.y);
            mma_f16(acc[nt], A1[1], vb.z, vb.w);
        }
        mma_f16(zacc, A0[0], ONE2, ONE2);
        mma_f16(zacc, A0[1], ONE2, ONE2);
        mma_f16(zacc, A1[0], ONE2, ONE2);
        mma_f16(zacc, A1[1], ONE2, ONE2);
        __syncthreads();
    }

    const float iz0 = 1.0f / zacc[0];
    const float iz1 = 1.0f / zacc[2];

    const int cb = c * 2;
    float* o0 = out + (size_t)irow0 * OF + head * HD + cb;
    float* o1 = out + (size_t)irow1 * OF + head * HD + cb;
#pragma unroll
    for (int nt = 0; nt < 8; nt++) {
        *(float2*)(o0 + nt * 8) = make_float2(acc[nt][0] * iz0, acc[nt][1] * iz0);
        *(float2*)(o1 + nt * 8) = make_float2(acc[nt][2] * iz1, acc[nt][3] * iz1);
    }
}

// ---------------- launch ----------------
extern "C" void kernel_launch(void* const* d_in, const int* in_sizes, int n_in,
                              void* d_out, int out_size) {
    const float* x     = (const float*)d_in[0];
    const int*   adj   = (const int*)d_in[1];
    const float* W     = (const float*)d_in[2];
    const float* a_src = (const float*)d_in[3];
    const float* a_dst = (const float*)d_in[4];
    float* out = (float*)d_out;

    __nv_bfloat16 *x1, *x2, *w1, *w2;
    cudaGetSymbolAddress((void**)&x1, g_X1);
    cudaGetSymbolAddress((void**)&x2, g_X2);
    cudaGetSymbolAddress((void**)&w1, g_W1);
    cudaGetSymbolAddress((void**)&w2, g_W2);

    fsplit_kernel<<<(NN * INF) / 1024, 256>>>(x, x1, x2);
    fsplit_kernel<<<(OF * INF) / 1024, 256>>>(W, w1, w2);
    mask_kernel<<<(NN * (NN / 256) * 32) / 256, 256>>>(adj);
    gemm_kernel<<<dim3(NN / 96, OF / 128), 384>>>();
    htrans_kernel<<<dim3(NN / 32, NH), 256>>>(a_src, a_dst);
    qred_kernel<<<NH, 256>>>();
    attn_kernel<<<dim3(NN / MT, NH), 384>>>(out);
}

// round 13
// speedup vs baseline: 1.4255x; 1.0167x over previous
#include <cuda_runtime.h>
#include <cuda_bf16.h>
#include <cuda_fp16.h>
#include <cstdint>

#define NN   3072
#define INF  512
#define NH   8
#define HD   64
#define OF   512   // NH*HD
#define MW   96    // mask words per row
#define KT2  64    // attn j double-tile
#define MT   192   // attn i tile per CTA (12 warps x 16 i)
#define NT2  (NN / KT2)

// ---------------- scratch ----------------
__device__ float         g_h[NN * OF];
__device__ float         g_P[NH * NN];
__device__ float         g_p[NH * NN];
__device__ float         g_Q[NH * NN];
__device__ float         g_q[NH * NN];
__device__ unsigned      g_QmU[NH];
__device__ unsigned      g_qmU[NH];
__device__ unsigned      g_mask[NN * MW];
__device__ __half        g_hTh[NH * HD * NN];      // [h][d][n], fp16 h (transposed)
__device__ __nv_bfloat16 g_X1[NN * INF];
__device__ __nv_bfloat16 g_X2[NN * INF];
__device__ __nv_bfloat16 g_W1[OF * INF];
__device__ __nv_bfloat16 g_W2[OF * INF];

__device__ __forceinline__ uint32_t smem_u32(const void* p) {
    uint32_t a;
    asm("{ .reg .u64 t; cvta.to.shared.u64 t, %1; cvt.u32.u64 %0, t; }" : "=r"(a) : "l"(p));
    return a;
}

__device__ __forceinline__ void mma_bf16(float* c, const uint32_t* a, uint32_t b0, uint32_t b1) {
    asm volatile(
        "mma.sync.aligned.m16n8k16.row.col.f32.bf16.bf16.f32 "
        "{%0,%1,%2,%3}, {%4,%5,%6,%7}, {%8,%9}, {%0,%1,%2,%3};"
        : "+f"(c[0]), "+f"(c[1]), "+f"(c[2]), "+f"(c[3])
        : "r"(a[0]), "r"(a[1]), "r"(a[2]), "r"(a[3]), "r"(b0), "r"(b1));
}

__device__ __forceinline__ void mma_f16(float* c, const uint32_t* a, uint32_t b0, uint32_t b1) {
    asm volatile(
        "mma.sync.aligned.m16n8k16.row.col.f32.f16.f16.f32 "
        "{%0,%1,%2,%3}, {%4,%5,%6,%7}, {%8,%9}, {%0,%1,%2,%3};"
        : "+f"(c[0]), "+f"(c[1]), "+f"(c[2]), "+f"(c[3])
        : "r"(a[0]), "r"(a[1]), "r"(a[2]), "r"(a[3]), "r"(b0), "r"(b1));
}

__device__ __forceinline__ void ldmx4(uint32_t* r, uint32_t addr) {
    asm volatile("ldmatrix.sync.aligned.m8n8.x4.shared.b16 {%0,%1,%2,%3}, [%4];"
                 : "=r"(r[0]), "=r"(r[1]), "=r"(r[2]), "=r"(r[3]) : "r"(addr));
}

__device__ __forceinline__ void split2(float w0, float w1, uint32_t& hi, uint32_t& lo) {
    uint32_t h;
    asm("cvt.rn.bf16x2.f32 %0, %1, %2;" : "=r"(h) : "f"(w1), "f"(w0));
    float r0 = w0 - __uint_as_float(h << 16);
    float r1 = w1 - __uint_as_float(h & 0xffff0000u);
    uint32_t l;
    asm("cvt.rn.bf16x2.f32 %0, %1, %2;" : "=r"(l) : "f"(r1), "f"(r0));
    hi = h; lo = l;
}

__device__ __forceinline__ uint32_t packh2(float b, float a) {
    uint32_t r;
    asm("cvt.rn.f16x2.f32 %0, %1, %2;" : "=r"(r) : "f"(b), "f"(a));
    return r;
}

// ---------------- Kernel 0: fp32 -> bf16 hi/lo split (X and W in one launch) ----------------
__global__ __launch_bounds__(256) void fsplit_kernel(const float* __restrict__ x,
                                                     const float* __restrict__ Wm) {
    const int gidx = blockIdx.x * blockDim.x + threadIdx.x;
    if (blockIdx.x == 0 && threadIdx.x < 2 * NH) {
        if (threadIdx.x < NH) g_QmU[threadIdx.x] = 0u;
        else                  g_qmU[threadIdx.x - NH] = 0u;
    }
    const int idx = gidx * 4;
    const float* src;
    __nv_bfloat16 *dhi, *dlo;
    int off;
    if (idx < NN * INF) {
        src = x; dhi = g_X1; dlo = g_X2; off = idx;
    } else {
        src = Wm; dhi = g_W1; dlo = g_W2; off = idx - NN * INF;
    }
    float4 v = *(const float4*)(src + off);
    uint32_t h0, h1, l0, l1;
    split2(v.x, v.y, h0, l0);
    split2(v.z, v.w, h1, l1);
    *(uint2*)(dhi + off) = make_uint2(h0, h1);
    *(uint2*)(dlo + off) = make_uint2(l0, l1);
}

// ---------------- Kernel 1: g_h = X @ W^T (bf16-split HMMA, 1 sync/iter) ----------------
// CTA = 96m x 128n, BK=32, grid (32, 4) = 128 CTAs -> single wave.
__global__ __launch_bounds__(384) void gemm_kernel() {
    __shared__ __align__(16) unsigned char Ah[2][96 * 64];
    __shared__ __align__(16) unsigned char Al[2][96 * 64];
    __shared__ __align__(16) unsigned char Bh[2][128 * 64];
    __shared__ __align__(16) unsigned char Bl[2][128 * 64];

    const int tid = threadIdx.x;
    const int w   = tid >> 5;
    const int L   = tid & 31;
    const int bm  = blockIdx.x * 96;
    const int bn  = blockIdx.y * 128;

    const int arow   = tid >> 2;
    const int achunk = tid & 3;
    const uint32_t aoff = (uint32_t)(arow * 64 + ((achunk ^ ((arow >> 1) & 3)) << 4));
    const int brow0  = tid >> 2;
    const int bchunk = tid & 3;
    const uint32_t boff0 = (uint32_t)(brow0 * 64 + ((bchunk ^ ((brow0 >> 1) & 3)) << 4));
    const int brow1  = 96 + (tid >> 2);
    const uint32_t boff1 = (uint32_t)(brow1 * 64 + ((bchunk ^ ((brow1 >> 1) & 3)) << 4));
    const bool hasB1 = tid < 128;

    const int warp_m = (w >> 2) * 32;
    const int warp_n = (w & 3) * 32;

    float acc[2][4][4];
#pragma unroll
    for (int mg = 0; mg < 2; mg++)
#pragma unroll
        for (int ng = 0; ng < 4; ng++)
#pragma unroll
            for (int k = 0; k < 4; k++) acc[mg][ng][k] = 0.f;

    uint4 xa_h, xa_l, wb_h0, wb_l0, wb_h1, wb_l1;
    // load + store tile 0, then preload tile 1 regs
    {
        const size_t ao = (size_t)(bm + arow) * INF + achunk * 8;
        xa_h = *(const uint4*)(g_X1 + ao);
        xa_l = *(const uint4*)(g_X2 + ao);
        const size_t bo0 = (size_t)(bn + brow0) * INF + bchunk * 8;
        wb_h0 = *(const uint4*)(g_W1 + bo0);
        wb_l0 = *(const uint4*)(g_W2 + bo0);
        if (hasB1) {
            const size_t bo1 = (size_t)(bn + brow1) * INF + bchunk * 8;
            wb_h1 = *(const uint4*)(g_W1 + bo1);
            wb_l1 = *(const uint4*)(g_W2 + bo1);
        }
        *(uint4*)&Ah[0][aoff]  = xa_h;
        *(uint4*)&Al[0][aoff]  = xa_l;
        *(uint4*)&Bh[0][boff0] = wb_h0;
        *(uint4*)&Bl[0][boff0] = wb_l0;
        if (hasB1) {
            *(uint4*)&Bh[0][boff1] = wb_h1;
            *(uint4*)&Bl[0][boff1] = wb_l1;
        }
        const size_t ao1 = ao + 32;
        xa_h = *(const uint4*)(g_X1 + ao1);
        xa_l = *(const uint4*)(g_X2 + ao1);
        wb_h0 = *(const uint4*)(g_W1 + bo0 + 32);
        wb_l0 = *(const uint4*)(g_W2 + bo0 + 32);
        if (hasB1) {
            const size_t bo1 = (size_t)(bn + brow1) * INF + bchunk * 8 + 32;
            wb_h1 = *(const uint4*)(g_W1 + bo1);
            wb_l1 = *(const uint4*)(g_W2 + bo1);
        }
    }
    __syncthreads();

    for (int it = 0; it < INF / 32; it++) {
        const int buf = it & 1;
        const int nbuf = buf ^ 1;

        const uint32_t aAh = smem_u32(&Ah[buf][0]);
        const uint32_t aAl = smem_u32(&Al[buf][0]);
        const uint32_t aBh = smem_u32(&Bh[buf][0]);
        const uint32_t aBl = smem_u32(&Bl[buf][0]);

        uint32_t bh[4][4], bl[4][4];
#pragma unroll
        for (int ng = 0; ng < 4; ng++) {
            const int row = warp_n + ng * 8 + (L & 7);
            const int ch  = L >> 3;
            const uint32_t off = (uint32_t)(row * 64 + ((ch ^ ((row >> 1) & 3)) << 4));
            ldmx4(bh[ng], aBh + off);
            ldmx4(bl[ng], aBl + off);
        }
        uint32_t ah[2][2][4], al[2][2][4];
#pragma unroll
        for (int mg = 0; mg < 2; mg++)
#pragma unroll
            for (int ks = 0; ks < 2; ks++) {
                const int mat = L >> 3;
                const int row = warp_m + mg * 16 + (L & 7) + (mat & 1) * 8;
                const int ch  = ks * 2 + (mat >> 1);
                const uint32_t off = (uint32_t)(row * 64 + ((ch ^ ((row >> 1) & 3)) << 4));
                ldmx4(ah[mg][ks], aAh + off);
                ldmx4(al[mg][ks], aAl + off);
            }

        // store prefetched tile it+1 into the other buffer
        if (it + 1 < INF / 32) {
            *(uint4*)&Ah[nbuf][aoff]  = xa_h;
            *(uint4*)&Al[nbuf][aoff]  = xa_l;
            *(uint4*)&Bh[nbuf][boff0] = wb_h0;
            *(uint4*)&Bl[nbuf][boff0] = wb_l0;
            if (hasB1) {
                *(uint4*)&Bh[nbuf][boff1] = wb_h1;
                *(uint4*)&Bl[nbuf][boff1] = wb_l1;
            }
        }
        // prefetch tile it+2
        if (it + 2 < INF / 32) {
            const int k0 = (it + 2) * 32;
            const size_t ao = (size_t)(bm + arow) * INF + k0 + achunk * 8;
            xa_h = *(const uint4*)(g_X1 + ao);
            xa_l = *(const uint4*)(g_X2 + ao);
            const size_t bo0 = (size_t)(bn + brow0) * INF + k0 + bchunk * 8;
            wb_h0 = *(const uint4*)(g_W1 + bo0);
            wb_l0 = *(const uint4*)(g_W2 + bo0);
            if (hasB1) {
                const size_t bo1 = (size_t)(bn + brow1) * INF + k0 + bchunk * 8;
                wb_h1 = *(const uint4*)(g_W1 + bo1);
                wb_l1 = *(const uint4*)(g_W2 + bo1);
            }
        }

#pragma unroll
        for (int mg = 0; mg < 2; mg++)
#pragma unroll
            for (int ng = 0; ng < 4; ng++)
#pragma unroll
                for (int ks = 0; ks < 2; ks++) {
                    mma_bf16(acc[mg][ng], ah[mg][ks], bh[ng][2*ks], bh[ng][2*ks+1]);
                    mma_bf16(acc[mg][ng], ah[mg][ks], bl[ng][2*ks], bl[ng][2*ks+1]);
                    mma_bf16(acc[mg][ng], al[mg][ks], bh[ng][2*ks], bh[ng][2*ks+1]);
                }
        __syncthreads();
    }

#pragma unroll
    for (int mg = 0; mg < 2; mg++)
#pragma unroll
        for (int ng = 0; ng < 4; ng++) {
            const int row = bm + warp_m + mg * 16 + (L >> 2);
            const int col = bn + warp_n + ng * 8 + (L & 3) * 2;
            *(float2*)(g_h + (size_t)row * OF + col)       = make_float2(acc[mg][ng][0], acc[mg][ng][1]);
            *(float2*)(g_h + (size_t)(row + 8) * OF + col) = make_float2(acc[mg][ng][2], acc[mg][ng][3]);
        }
}

// ---------------- Kernel 3: adjacency (+diag) bitmask, MLP=4 ----------------
// Warp = 512 cols of one row; lane loads 4 int4.
__global__ __launch_bounds__(256) void mask_kernel(const int* __restrict__ adj) {
    const int gw = (blockIdx.x * blockDim.x + threadIdx.x) >> 5;
    const int L  = threadIdx.x & 31;
    const int i  = gw / (NN / 512);
    const int sp = gw % (NN / 512);
    const int cb = sp * 512 + L * 4;
    unsigned val[4];
#pragma unroll
    for (int k = 0; k < 4; k++) {
        const int c = cb + k * 128;
        const int4 v = *(const int4*)(adj + (size_t)i * NN + c);
        unsigned nib = ((v.x != 0 || c     == i) ? 1u : 0u)
                     | ((v.y != 0 || c + 1 == i) ? 2u : 0u)
                     | ((v.z != 0 || c + 2 == i) ? 4u : 0u)
                     | ((v.w != 0 || c + 3 == i) ? 8u : 0u);
        val[k] = nib << ((L & 7) * 4);
    }
#pragma unroll
    for (int k = 0; k < 4; k++) {
        val[k] |= __shfl_xor_sync(0xffffffffu, val[k], 1);
        val[k] |= __shfl_xor_sync(0xffffffffu, val[k], 2);
        val[k] |= __shfl_xor_sync(0xffffffffu, val[k], 4);
    }
    if ((L & 7) == 0) {
        const int base = i * MW + sp * 16 + (L >> 3);
#pragma unroll
        for (int k = 0; k < 4; k++) g_mask[base + k * 4] = val[k];
    }
}

// ---------------- Kernel 3b: fused transpose(fp16) + coef + per-head max ----------------
__global__ __launch_bounds__(256) void htrans_kernel(const float* __restrict__ a_src,
                                                     const float* __restrict__ a_dst) {
    __shared__ float tl[32][65];
    const int h  = blockIdx.y;
    const int n0 = blockIdx.x * 32;
    const int t  = threadIdx.x;
    const int r  = t >> 3;
    const int c8 = (t & 7) * 8;
    {
        const float* src = g_h + (size_t)(n0 + r) * OF + h * HD + c8;
        float4 v0 = *(const float4*)src;
        float4 v1 = *(const float4*)(src + 4);
        tl[r][c8+0] = v0.x; tl[r][c8+1] = v0.y; tl[r][c8+2] = v0.z; tl[r][c8+3] = v0.w;
        tl[r][c8+4] = v1.x; tl[r][c8+5] = v1.y; tl[r][c8+6] = v1.z; tl[r][c8+7] = v1.w;

        const float4* as = (const float4*)(a_src + h * HD + c8);
        const float4* ad = (const float4*)(a_dst + h * HD + c8);
        float4 a0 = as[0], a1 = as[1], d0 = ad[0], d1 = ad[1];
        float s = v0.x*a0.x + v0.y*a0.y + v0.z*a0.z + v0.w*a0.w
                + v1.x*a1.x + v1.y*a1.y + v1.z*a1.z + v1.w*a1.w;
        float tt = v0.x*d0.x + v0.y*d0.y + v0.z*d0.z + v0.w*d0.w
                 + v1.x*d1.x + v1.y*d1.y + v1.z*d1.z + v1.w*d1.w;
        s  += __shfl_xor_sync(0xffffffffu, s, 1);
        tt += __shfl_xor_sync(0xffffffffu, tt, 1);
        s  += __shfl_xor_sync(0xffffffffu, s, 2);
        tt += __shfl_xor_sync(0xffffffffu, tt, 2);
        s  += __shfl_xor_sync(0xffffffffu, s, 4);
        tt += __shfl_xor_sync(0xffffffffu, tt, 4);
        float Qc = 0.f, qc = 0.f;
        if ((t & 7) == 0) {
            const int idx = h * NN + n0 + r;
            const float eS  = __expf(s);
            const float eS2 = __expf(0.2f * s);
            Qc = __expf(tt);
            qc = __expf(0.2f * tt);
            g_P[idx] = eS;
            g_p[idx] = eS2;
            g_Q[idx] = Qc;
            g_q[idx] = qc;
        }
        // per-head max of Q, q (fused qred)
        Qc = fmaxf(Qc, __shfl_xor_sync(0xffffffffu, Qc, 8));
        qc = fmaxf(qc, __shfl_xor_sync(0xffffffffu, qc, 8));
        Qc = fmaxf(Qc, __shfl_xor_sync(0xffffffffu, Qc, 16));
        qc = fmaxf(qc, __shfl_xor_sync(0xffffffffu, qc, 16));
        if ((t & 31) == 0) {
            atomicMax(&g_QmU[h], __float_as_uint(Qc));
            atomicMax(&g_qmU[h], __float_as_uint(qc));
        }
    }
    __syncthreads();
    const int d  = t >> 2;
    const int ns = (t & 3) * 8;
    uint32_t o0[4];
#pragma unroll
    for (int k = 0; k < 4; k++)
        o0[k] = packh2(tl[ns + 2*k + 1][d], tl[ns + 2*k][d]);
    *(uint4*)(g_hTh + (size_t)(h * HD + d) * NN + n0 + ns) = make_uint4(o0[0], o0[1], o0[2], o0[3]);
}

// ---------------- Kernel 4: fp16 MMA masked softmax-aggregate, KT=64, 1 sync/iter ----------------
__global__ __launch_bounds__(384) void attn_kernel(float* __restrict__ out) {
    __shared__ __align__(16) unsigned char Bsm[2][2][HD * 64];  // [buf][half] 4KB each
    __shared__ __align__(8)  float2 QQ[2][KT2];

    const int tid  = threadIdx.x;
    const int w    = tid >> 5;
    const int L    = tid & 31;
    const int head = blockIdx.y;
    const int i0   = blockIdx.x * MT;

    const bool stager = tid < 256;
    const int sd = (tid >> 2) & 63;
    const int q4 = tid & 3;
    const __half* hp = g_hTh + (size_t)(head * HD + sd) * NN;
    const int skey = sd & 3;
    const int ppos = q4 * 4;

    const int gr = L >> 2;
    const int c  = L & 3;
    const int irow0 = i0 + w * 16 + gr;
    const int irow1 = irow0 + 8;
    const float Qm = __uint_as_float(g_QmU[head]);
    const float qm = __uint_as_float(g_qmU[head]);
    const float P0r = g_P[head * NN + irow0], p0r = g_p[head * NN + irow0];
    const float P1r = g_P[head * NN + irow1], p1r = g_p[head * NN + irow1];
    const float sc0 = 1.0f / (P0r * Qm + p0r * qm);
    const float sc1 = 1.0f / (P1r * Qm + p1r * qm);
    const float P0 = P0r * sc0, p0 = p0r * sc0;
    const float P1 = P1r * sc1, p1 = p1r * sc1;
    const unsigned* mrow0 = g_mask + (size_t)irow0 * MW;
    const unsigned* mrow1 = g_mask + (size_t)irow1 * MW;

    const uint32_t ONE2 = 0x3C003C00u;

    float acc[8][4];
#pragma unroll
    for (int n = 0; n < 8; n++)
#pragma unroll
        for (int k = 0; k < 4; k++) acc[n][k] = 0.f;
    float zacc[4] = {0.f, 0.f, 0.f, 0.f};

    // ---- prologue: load+store tile0, prefetch tile1 ----
    uint4 nva, nvb;
    if (stager) {
        nva = *(const uint4*)(hp + q4 * 8);
        nvb = *(const uint4*)(hp + 32 + q4 * 8);
        unsigned char* ba = &Bsm[0][0][sd * 64];
        unsigned char* bb = &Bsm[0][1][sd * 64];
        *(uint32_t*)(ba + (((0 ^ skey) << 4) + ppos)) = nva.x;
        *(uint32_t*)(ba + (((1 ^ skey) << 4) + ppos)) = nva.y;
        *(uint32_t*)(ba + (((2 ^ skey) << 4) + ppos)) = nva.z;
        *(uint32_t*)(ba + (((3 ^ skey) << 4) + ppos)) = nva.w;
        *(uint32_t*)(bb + (((0 ^ skey) << 4) + ppos)) = nvb.x;
        *(uint32_t*)(bb + (((1 ^ skey) << 4) + ppos)) = nvb.y;
        *(uint32_t*)(bb + (((2 ^ skey) << 4) + ppos)) = nvb.z;
        *(uint32_t*)(bb + (((3 ^ skey) << 4) + ppos)) = nvb.w;
        nva = *(const uint4*)(hp + KT2 + q4 * 8);
        nvb = *(const uint4*)(hp + KT2 + 32 + q4 * 8);
    }
    if (tid < KT2)
        QQ[0][tid] = make_float2(g_Q[head * NN + tid], g_q[head * NN + tid]);
    unsigned cm0a = mrow0[0], cm0b = mrow0[1];
    unsigned cm1a = mrow1[0], cm1b = mrow1[1];
    unsigned nm0a = mrow0[2], nm0b = mrow0[3];
    unsigned nm1a = mrow1[2], nm1b = mrow1[3];
    float nQ = 0.f, nq = 0.f;
    if (tid < KT2) {
        nQ = g_Q[head * NN + KT2 + tid];
        nq = g_q[head * NN + KT2 + tid];
    }
    __syncthreads();

    for (int t = 0; t < NT2; t++) {
        const int buf = t & 1;
        const int nbuf = buf ^ 1;

        // store prefetched tile t+1 into the other buffer
        if (t + 1 < NT2) {
            if (stager) {
                unsigned char* ba = &Bsm[nbuf][0][sd * 64];
                unsigned char* bb = &Bsm[nbuf][1][sd * 64];
                *(uint32_t*)(ba + (((0 ^ skey) << 4) + ppos)) = nva.x;
                *(uint32_t*)(ba + (((1 ^ skey) << 4) + ppos)) = nva.y;
                *(uint32_t*)(ba + (((2 ^ skey) << 4) + ppos)) = nva.z;
                *(uint32_t*)(ba + (((3 ^ skey) << 4) + ppos)) = nva.w;
                *(uint32_t*)(bb + (((0 ^ skey) << 4) + ppos)) = nvb.x;
                *(uint32_t*)(bb + (((1 ^ skey) << 4) + ppos)) = nvb.y;
                *(uint32_t*)(bb + (((2 ^ skey) << 4) + ppos)) = nvb.z;
                *(uint32_t*)(bb + (((3 ^ skey) << 4) + ppos)) = nvb.w;
            }
            if (tid < KT2) QQ[nbuf][tid] = make_float2(nQ, nq);
        }

        // ---- A fragments (tile t) from QQ[buf] + cm masks ----
        uint32_t A0[2][4], A1[2][4];
#pragma unroll
        for (int hf = 0; hf < 2; hf++) {
            const unsigned m0 = hf ? cm0b : cm0a;
            const unsigned m1 = hf ? cm1b : cm1a;
            uint32_t (*A)[4] = hf ? A1 : A0;
#pragma unroll
            for (int s = 0; s < 2; s++) {
                const int ja = 16 * s + 2 * c;
                const int jq = hf * 32 + ja;
                float2 qa0 = QQ[buf][jq];
                float2 qa1 = QQ[buf][jq + 1];
                float2 qb0 = QQ[buf][jq + 8];
                float2 qb1 = QQ[buf][jq + 9];
                float w00 = fmaxf(P0 * qa0.x, p0 * qa0.y); w00 = ((m0 >> ja)       & 1u) ? w00 : 0.f;
                float w01 = fmaxf(P0 * qa1.x, p0 * qa1.y); w01 = ((m0 >> (ja + 1)) & 1u) ? w01 : 0.f;
                float w02 = fmaxf(P0 * qb0.x, p0 * qb0.y); w02 = ((m0 >> (ja + 8)) & 1u) ? w02 : 0.f;
                float w03 = fmaxf(P0 * qb1.x, p0 * qb1.y); w03 = ((m0 >> (ja + 9)) & 1u) ? w03 : 0.f;
                float w10 = fmaxf(P1 * qa0.x, p1 * qa0.y); w10 = ((m1 >> ja)       & 1u) ? w10 : 0.f;
                float w11 = fmaxf(P1 * qa1.x, p1 * qa1.y); w11 = ((m1 >> (ja + 1)) & 1u) ? w11 : 0.f;
                float w12 = fmaxf(P1 * qb0.x, p1 * qb0.y); w12 = ((m1 >> (ja + 8)) & 1u) ? w12 : 0.f;
                float w13 = fmaxf(P1 * qb1.x, p1 * qb1.y); w13 = ((m1 >> (ja + 9)) & 1u) ? w13 : 0.f;
                A[s][0] = packh2(w01, w00);
                A[s][1] = packh2(w11, w10);
                A[s][2] = packh2(w03, w02);
                A[s][3] = packh2(w13, w12);
            }
        }

        // prefetch tile t+2 + rotate masks
        cm0a = nm0a; cm0b = nm0b; cm1a = nm1a; cm1b = nm1b;
        if (t + 2 < NT2) {
            const int j0 = (t + 2) * KT2;
            if (stager) {
                nva = *(const uint4*)(hp + j0 + q4 * 8);
                nvb = *(const uint4*)(hp + j0 + 32 + q4 * 8);
            }
            nm0a = mrow0[2 * (t + 2)];
            nm0b = mrow0[2 * (t + 2) + 1];
            nm1a = mrow1[2 * (t + 2)];
            nm1b = mrow1[2 * (t + 2) + 1];
            if (tid < KT2) {
                nQ = g_Q[head * NN + j0 + tid];
                nq = g_q[head * NN + j0 + tid];
            }
        }

        // ---- B fragment loads + MMA ----
#pragma unroll
        for (int nt = 0; nt < 8; nt++) {
            const int d = nt * 8 + gr;
            const uint32_t off = (uint32_t)(d * 64 + ((c ^ (gr & 3)) << 4));
            uint4 va = *(const uint4*)(&Bsm[buf][0][off]);
            uint4 vb = *(const uint4*)(&Bsm[buf][1][off]);
            mma_f16(acc[nt], A0[0], va.x, va.y);
            mma_f16(acc[nt], A0[1], va.z, va.w);
            mma_f16(acc[nt], A1[0], vb.x, vb.y);
            mma_f16(acc[nt], A1[1], vb.z, vb.w);
        }
        mma_f16(zacc, A0[0], ONE2, ONE2);
        mma_f16(zacc, A0[1], ONE2, ONE2);
        mma_f16(zacc, A1[0], ONE2, ONE2);
        mma_f16(zacc, A1[1], ONE2, ONE2);
        __syncthreads();
    }

    const float iz0 = 1.0f / zacc[0];
    const float iz1 = 1.0f / zacc[2];

    const int cb = c * 2;
    float* o0 = out + (size_t)irow0 * OF + head * HD + cb;
    float* o1 = out + (size_t)irow1 * OF + head * HD + cb;
#pragma unroll
    for (int nt = 0; nt < 8; nt++) {
        *(float2*)(o0 + nt * 8) = make_float2(acc[nt][0] * iz0, acc[nt][1] * iz0);
        *(float2*)(o1 + nt * 8) = make_float2(acc[nt][2] * iz1, acc[nt][3] * iz1);
    }
}

// ---------------- launch ----------------
extern "C" void kernel_launch(void* const* d_in, const int* in_sizes, int n_in,
                              void* d_out, int out_size) {
    const float* x     = (const float*)d_in[0];
    const int*   adj   = (const int*)d_in[1];
    const float* W     = (const float*)d_in[2];
    const float* a_src = (const float*)d_in[3];
    const float* a_dst = (const float*)d_in[4];
    float* out = (float*)d_out;

    fsplit_kernel<<<((NN + OF) * INF) / 1024, 256>>>(x, W);
    mask_kernel<<<(NN * (NN / 512) * 32) / 256, 256>>>(adj);
    gemm_kernel<<<dim3(NN / 96, OF / 128), 384>>>();
    htrans_kernel<<<dim3(NN / 32, NH), 256>>>(a_src, a_dst);
    attn_kernel<<<dim3(NN / MT, NH), 384>>>(out);
}

// round 14
// speedup vs baseline: 1.4579x; 1.0227x over previous
#include <cuda_runtime.h>
#include <cuda_bf16.h>
#include <cuda_fp16.h>
#include <cstdint>

#define NN   3072
#define INF  512
#define NH   8
#define HD   64
#define OF   512   // NH*HD
#define MW   96    // mask words per row
#define KT2  64    // attn j double-tile
#define MT   192   // attn i tile per CTA (6 i-ranges x 32 i)
#define NT2  (NN / KT2)

// ---------------- scratch ----------------
__device__ float         g_h[NN * OF];
__device__ float         g_P[NH * NN];
__device__ float         g_p[NH * NN];
__device__ float         g_Q[NH * NN];
__device__ float         g_q[NH * NN];
__device__ unsigned      g_QmU[NH];
__device__ unsigned      g_qmU[NH];
__device__ unsigned      g_mask[NN * MW];
__device__ __half        g_hTh[NH * HD * NN];      // [h][d][n], fp16 h (transposed)
__device__ __nv_bfloat16 g_X1[NN * INF];
__device__ __nv_bfloat16 g_X2[NN * INF];
__device__ __nv_bfloat16 g_W1[OF * INF];
__device__ __nv_bfloat16 g_W2[OF * INF];

__device__ __forceinline__ uint32_t smem_u32(const void* p) {
    uint32_t a;
    asm("{ .reg .u64 t; cvta.to.shared.u64 t, %1; cvt.u32.u64 %0, t; }" : "=r"(a) : "l"(p));
    return a;
}

__device__ __forceinline__ void mma_bf16(float* c, const uint32_t* a, uint32_t b0, uint32_t b1) {
    asm volatile(
        "mma.sync.aligned.m16n8k16.row.col.f32.bf16.bf16.f32 "
        "{%0,%1,%2,%3}, {%4,%5,%6,%7}, {%8,%9}, {%0,%1,%2,%3};"
        : "+f"(c[0]), "+f"(c[1]), "+f"(c[2]), "+f"(c[3])
        : "r"(a[0]), "r"(a[1]), "r"(a[2]), "r"(a[3]), "r"(b0), "r"(b1));
}

__device__ __forceinline__ void mma_f16(float* c, const uint32_t* a, uint32_t b0, uint32_t b1) {
    asm volatile(
        "mma.sync.aligned.m16n8k16.row.col.f32.f16.f16.f32 "
        "{%0,%1,%2,%3}, {%4,%5,%6,%7}, {%8,%9}, {%0,%1,%2,%3};"
        : "+f"(c[0]), "+f"(c[1]), "+f"(c[2]), "+f"(c[3])
        : "r"(a[0]), "r"(a[1]), "r"(a[2]), "r"(a[3]), "r"(b0), "r"(b1));
}

__device__ __forceinline__ void ldmx4(uint32_t* r, uint32_t addr) {
    asm volatile("ldmatrix.sync.aligned.m8n8.x4.shared.b16 {%0,%1,%2,%3}, [%4];"
                 : "=r"(r[0]), "=r"(r[1]), "=r"(r[2]), "=r"(r[3]) : "r"(addr));
}

__device__ __forceinline__ void split2(float w0, float w1, uint32_t& hi, uint32_t& lo) {
    uint32_t h;
    asm("cvt.rn.bf16x2.f32 %0, %1, %2;" : "=r"(h) : "f"(w1), "f"(w0));
    float r0 = w0 - __uint_as_float(h << 16);
    float r1 = w1 - __uint_as_float(h & 0xffff0000u);
    uint32_t l;
    asm("cvt.rn.bf16x2.f32 %0, %1, %2;" : "=r"(l) : "f"(r1), "f"(r0));
    hi = h; lo = l;
}

__device__ __forceinline__ uint32_t packh2(float b, float a) {
    uint32_t r;
    asm("cvt.rn.f16x2.f32 %0, %1, %2;" : "=r"(r) : "f"(b), "f"(a));
    return r;
}

// ---------------- Kernel 0: fp32 -> bf16 hi/lo split (X and W, MLP=2) ----------------
__global__ __launch_bounds__(256) void fsplit_kernel(const float* __restrict__ x,
                                                     const float* __restrict__ Wm) {
    const int gidx = blockIdx.x * blockDim.x + threadIdx.x;
    if (blockIdx.x == 0 && threadIdx.x < 2 * NH) {
        if (threadIdx.x < NH) g_QmU[threadIdx.x] = 0u;
        else                  g_qmU[threadIdx.x - NH] = 0u;
    }
    const int idx = gidx * 8;
    const float* src;
    __nv_bfloat16 *dhi, *dlo;
    int off;
    if (idx < NN * INF) {
        src = x; dhi = g_X1; dlo = g_X2; off = idx;
    } else {
        src = Wm; dhi = g_W1; dlo = g_W2; off = idx - NN * INF;
    }
    float4 v0 = *(const float4*)(src + off);
    float4 v1 = *(const float4*)(src + off + 4);
    uint32_t h0, h1, h2, h3, l0, l1, l2, l3;
    split2(v0.x, v0.y, h0, l0);
    split2(v0.z, v0.w, h1, l1);
    split2(v1.x, v1.y, h2, l2);
    split2(v1.z, v1.w, h3, l3);
    *(uint4*)(dhi + off) = make_uint4(h0, h1, h2, h3);
    *(uint4*)(dlo + off) = make_uint4(l0, l1, l2, l3);
}

// ---------------- Kernel 1: g_h = X @ W^T (bf16-split HMMA, 1 sync/iter) ----------------
__global__ __launch_bounds__(384) void gemm_kernel() {
    __shared__ __align__(16) unsigned char Ah[2][96 * 64];
    __shared__ __align__(16) unsigned char Al[2][96 * 64];
    __shared__ __align__(16) unsigned char Bh[2][128 * 64];
    __shared__ __align__(16) unsigned char Bl[2][128 * 64];

    const int tid = threadIdx.x;
    const int w   = tid >> 5;
    const int L   = tid & 31;
    const int bm  = blockIdx.x * 96;
    const int bn  = blockIdx.y * 128;

    const int arow   = tid >> 2;
    const int achunk = tid & 3;
    const uint32_t aoff = (uint32_t)(arow * 64 + ((achunk ^ ((arow >> 1) & 3)) << 4));
    const int brow0  = tid >> 2;
    const int bchunk = tid & 3;
    const uint32_t boff0 = (uint32_t)(brow0 * 64 + ((bchunk ^ ((brow0 >> 1) & 3)) << 4));
    const int brow1  = 96 + (tid >> 2);
    const uint32_t boff1 = (uint32_t)(brow1 * 64 + ((bchunk ^ ((brow1 >> 1) & 3)) << 4));
    const bool hasB1 = tid < 128;

    const int warp_m = (w >> 2) * 32;
    const int warp_n = (w & 3) * 32;

    float acc[2][4][4];
#pragma unroll
    for (int mg = 0; mg < 2; mg++)
#pragma unroll
        for (int ng = 0; ng < 4; ng++)
#pragma unroll
            for (int k = 0; k < 4; k++) acc[mg][ng][k] = 0.f;

    uint4 xa_h, xa_l, wb_h0, wb_l0, wb_h1, wb_l1;
    {
        const size_t ao = (size_t)(bm + arow) * INF + achunk * 8;
        xa_h = *(const uint4*)(g_X1 + ao);
        xa_l = *(const uint4*)(g_X2 + ao);
        const size_t bo0 = (size_t)(bn + brow0) * INF + bchunk * 8;
        wb_h0 = *(const uint4*)(g_W1 + bo0);
        wb_l0 = *(const uint4*)(g_W2 + bo0);
        if (hasB1) {
            const size_t bo1 = (size_t)(bn + brow1) * INF + bchunk * 8;
            wb_h1 = *(const uint4*)(g_W1 + bo1);
            wb_l1 = *(const uint4*)(g_W2 + bo1);
        }
        *(uint4*)&Ah[0][aoff]  = xa_h;
        *(uint4*)&Al[0][aoff]  = xa_l;
        *(uint4*)&Bh[0][boff0] = wb_h0;
        *(uint4*)&Bl[0][boff0] = wb_l0;
        if (hasB1) {
            *(uint4*)&Bh[0][boff1] = wb_h1;
            *(uint4*)&Bl[0][boff1] = wb_l1;
        }
        const size_t ao1 = ao + 32;
        xa_h = *(const uint4*)(g_X1 + ao1);
        xa_l = *(const uint4*)(g_X2 + ao1);
        wb_h0 = *(const uint4*)(g_W1 + bo0 + 32);
        wb_l0 = *(const uint4*)(g_W2 + bo0 + 32);
        if (hasB1) {
            const size_t bo1 = (size_t)(bn + brow1) * INF + bchunk * 8 + 32;
            wb_h1 = *(const uint4*)(g_W1 + bo1);
            wb_l1 = *(const uint4*)(g_W2 + bo1);
        }
    }
    __syncthreads();

    for (int it = 0; it < INF / 32; it++) {
        const int buf = it & 1;
        const int nbuf = buf ^ 1;

        const uint32_t aAh = smem_u32(&Ah[buf][0]);
        const uint32_t aAl = smem_u32(&Al[buf][0]);
        const uint32_t aBh = smem_u32(&Bh[buf][0]);
        const uint32_t aBl = smem_u32(&Bl[buf][0]);

        uint32_t bh[4][4], bl[4][4];
#pragma unroll
        for (int ng = 0; ng < 4; ng++) {
            const int row = warp_n + ng * 8 + (L & 7);
            const int ch  = L >> 3;
            const uint32_t off = (uint32_t)(row * 64 + ((ch ^ ((row >> 1) & 3)) << 4));
            ldmx4(bh[ng], aBh + off);
            ldmx4(bl[ng], aBl + off);
        }
        uint32_t ah[2][2][4], al[2][2][4];
#pragma unroll
        for (int mg = 0; mg < 2; mg++)
#pragma unroll
            for (int ks = 0; ks < 2; ks++) {
                const int mat = L >> 3;
                const int row = warp_m + mg * 16 + (L & 7) + (mat & 1) * 8;
                const int ch  = ks * 2 + (mat >> 1);
                const uint32_t off = (uint32_t)(row * 64 + ((ch ^ ((row >> 1) & 3)) << 4));
                ldmx4(ah[mg][ks], aAh + off);
                ldmx4(al[mg][ks], aAl + off);
            }

        if (it + 1 < INF / 32) {
            *(uint4*)&Ah[nbuf][aoff]  = xa_h;
            *(uint4*)&Al[nbuf][aoff]  = xa_l;
            *(uint4*)&Bh[nbuf][boff0] = wb_h0;
            *(uint4*)&Bl[nbuf][boff0] = wb_l0;
            if (hasB1) {
                *(uint4*)&Bh[nbuf][boff1] = wb_h1;
                *(uint4*)&Bl[nbuf][boff1] = wb_l1;
            }
        }
        if (it + 2 < INF / 32) {
            const int k0 = (it + 2) * 32;
            const size_t ao = (size_t)(bm + arow) * INF + k0 + achunk * 8;
            xa_h = *(const uint4*)(g_X1 + ao);
            xa_l = *(const uint4*)(g_X2 + ao);
            const size_t bo0 = (size_t)(bn + brow0) * INF + k0 + bchunk * 8;
            wb_h0 = *(const uint4*)(g_W1 + bo0);
            wb_l0 = *(const uint4*)(g_W2 + bo0);
            if (hasB1) {
                const size_t bo1 = (size_t)(bn + brow1) * INF + k0 + bchunk * 8;
                wb_h1 = *(const uint4*)(g_W1 + bo1);
                wb_l1 = *(const uint4*)(g_W2 + bo1);
            }
        }

#pragma unroll
        for (int mg = 0; mg < 2; mg++)
#pragma unroll
            for (int ng = 0; ng < 4; ng++)
#pragma unroll
                for (int ks = 0; ks < 2; ks++) {
                    mma_bf16(acc[mg][ng], ah[mg][ks], bh[ng][2*ks], bh[ng][2*ks+1]);
                    mma_bf16(acc[mg][ng], ah[mg][ks], bl[ng][2*ks], bl[ng][2*ks+1]);
                    mma_bf16(acc[mg][ng], al[mg][ks], bh[ng][2*ks], bh[ng][2*ks+1]);
                }
        __syncthreads();
    }

#pragma unroll
    for (int mg = 0; mg < 2; mg++)
#pragma unroll
        for (int ng = 0; ng < 4; ng++) {
            const int row = bm + warp_m + mg * 16 + (L >> 2);
            const int col = bn + warp_n + ng * 8 + (L & 3) * 2;
            *(float2*)(g_h + (size_t)row * OF + col)       = make_float2(acc[mg][ng][0], acc[mg][ng][1]);
            *(float2*)(g_h + (size_t)(row + 8) * OF + col) = make_float2(acc[mg][ng][2], acc[mg][ng][3]);
        }
}

// ---------------- Kernel 3: adjacency (+diag) bitmask, MLP=4 ----------------
__global__ __launch_bounds__(256) void mask_kernel(const int* __restrict__ adj) {
    const int gw = (blockIdx.x * blockDim.x + threadIdx.x) >> 5;
    const int L  = threadIdx.x & 31;
    const int i  = gw / (NN / 512);
    const int sp = gw % (NN / 512);
    const int cb = sp * 512 + L * 4;
    unsigned val[4];
#pragma unroll
    for (int k = 0; k < 4; k++) {
        const int c = cb + k * 128;
        const int4 v = *(const int4*)(adj + (size_t)i * NN + c);
        unsigned nib = ((v.x != 0 || c     == i) ? 1u : 0u)
                     | ((v.y != 0 || c + 1 == i) ? 2u : 0u)
                     | ((v.z != 0 || c + 2 == i) ? 4u : 0u)
                     | ((v.w != 0 || c + 3 == i) ? 8u : 0u);
        val[k] = nib << ((L & 7) * 4);
    }
#pragma unroll
    for (int k = 0; k < 4; k++) {
        val[k] |= __shfl_xor_sync(0xffffffffu, val[k], 1);
        val[k] |= __shfl_xor_sync(0xffffffffu, val[k], 2);
        val[k] |= __shfl_xor_sync(0xffffffffu, val[k], 4);
    }
    if ((L & 7) == 0) {
        const int base = i * MW + sp * 16 + (L >> 3);
#pragma unroll
        for (int k = 0; k < 4; k++) g_mask[base + k * 4] = val[k];
    }
}

// ---------------- Kernel 3b: fused transpose(fp16) + coef + per-head max ----------------
__global__ __launch_bounds__(256) void htrans_kernel(const float* __restrict__ a_src,
                                                     const float* __restrict__ a_dst) {
    __shared__ float tl[32][65];
    const int h  = blockIdx.y;
    const int n0 = blockIdx.x * 32;
    const int t  = threadIdx.x;
    const int r  = t >> 3;
    const int c8 = (t & 7) * 8;
    {
        const float* src = g_h + (size_t)(n0 + r) * OF + h * HD + c8;
        float4 v0 = *(const float4*)src;
        float4 v1 = *(const float4*)(src + 4);
        tl[r][c8+0] = v0.x; tl[r][c8+1] = v0.y; tl[r][c8+2] = v0.z; tl[r][c8+3] = v0.w;
        tl[r][c8+4] = v1.x; tl[r][c8+5] = v1.y; tl[r][c8+6] = v1.z; tl[r][c8+7] = v1.w;

        const float4* as = (const float4*)(a_src + h * HD + c8);
        const float4* ad = (const float4*)(a_dst + h * HD + c8);
        float4 a0 = as[0], a1 = as[1], d0 = ad[0], d1 = ad[1];
        float s = v0.x*a0.x + v0.y*a0.y + v0.z*a0.z + v0.w*a0.w
                + v1.x*a1.x + v1.y*a1.y + v1.z*a1.z + v1.w*a1.w;
        float tt = v0.x*d0.x + v0.y*d0.y + v0.z*d0.z + v0.w*d0.w
                 + v1.x*d1.x + v1.y*d1.y + v1.z*d1.z + v1.w*d1.w;
        s  += __shfl_xor_sync(0xffffffffu, s, 1);
        tt += __shfl_xor_sync(0xffffffffu, tt, 1);
        s  += __shfl_xor_sync(0xffffffffu, s, 2);
        tt += __shfl_xor_sync(0xffffffffu, tt, 2);
        s  += __shfl_xor_sync(0xffffffffu, s, 4);
        tt += __shfl_xor_sync(0xffffffffu, tt, 4);
        float Qc = 0.f, qc = 0.f;
        if ((t & 7) == 0) {
            const int idx = h * NN + n0 + r;
            const float eS  = __expf(s);
            const float eS2 = __expf(0.2f * s);
            Qc = __expf(tt);
            qc = __expf(0.2f * tt);
            g_P[idx] = eS;
            g_p[idx] = eS2;
            g_Q[idx] = Qc;
            g_q[idx] = qc;
        }
        Qc = fmaxf(Qc, __shfl_xor_sync(0xffffffffu, Qc, 8));
        qc = fmaxf(qc, __shfl_xor_sync(0xffffffffu, qc, 8));
        Qc = fmaxf(Qc, __shfl_xor_sync(0xffffffffu, Qc, 16));
        qc = fmaxf(qc, __shfl_xor_sync(0xffffffffu, qc, 16));
        if ((t & 31) == 0) {
            atomicMax(&g_QmU[h], __float_as_uint(Qc));
            atomicMax(&g_qmU[h], __float_as_uint(qc));
        }
    }
    __syncthreads();
    const int d  = t >> 2;
    const int ns = (t & 3) * 8;
    uint32_t o0[4];
#pragma unroll
    for (int k = 0; k < 4; k++)
        o0[k] = packh2(tl[ns + 2*k + 1][d], tl[ns + 2*k][d]);
    *(uint4*)(g_hTh + (size_t)(h * HD + d) * NN + n0 + ns) = make_uint4(o0[0], o0[1], o0[2], o0[3]);
}

// ---------------- Kernel 4: fp16 MMA softmax-aggregate, j-split warps ----------------
// CTA = 192 i x 1 head, 12 warps = 6 i-ranges (32 i) x 2 j-halves (32 j).
// Each warp: 32 i x 64 d x its 32 j -> loads only HALF the B tile (4KB/iter).
// Partial sums combined at the end: Z via smem exchange, out via write-then-add.
__global__ __launch_bounds__(384) void attn_kernel(float* __restrict__ out) {
    __shared__ __align__(16) unsigned char Bsm[2][2][HD * 64];  // [buf][half]
    __shared__ __align__(8)  float2 QQ[2][KT2];
    __shared__ float zsh[2][MT];

    const int tid  = threadIdx.x;
    const int w    = tid >> 5;
    const int L    = tid & 31;
    const int head = blockIdx.y;
    const int i0   = blockIdx.x * MT;

    const int ir = w % 6;            // i-range (32 rows)
    const int jh = w / 6;            // j-half

    const bool stager = tid < 256;
    const int sd = (tid >> 2) & 63;
    const int q4 = tid & 3;
    const __half* hp = g_hTh + (size_t)(head * HD + sd) * NN;
    const int skey = sd & 3;
    const int ppos = q4 * 4;

    const int gr = L >> 2;
    const int c  = L & 3;
    const int rbase = i0 + ir * 32;
    const float Qm = __uint_as_float(g_QmU[head]);
    const float qm = __uint_as_float(g_qmU[head]);
    float Ps[4], ps[4];
    const unsigned* mp[4];
#pragma unroll
    for (int k = 0; k < 4; k++) {
        const int r = rbase + gr + k * 8;
        const float Pr = g_P[head * NN + r];
        const float pr = g_p[head * NN + r];
        const float sc = 1.0f / (Pr * Qm + pr * qm);
        Ps[k] = Pr * sc;
        ps[k] = pr * sc;
        mp[k] = g_mask + (size_t)r * MW;
    }

    const uint32_t ONE2 = 0x3C003C00u;

    float acc[2][8][4];
#pragma unroll
    for (int mg = 0; mg < 2; mg++)
#pragma unroll
        for (int n = 0; n < 8; n++)
#pragma unroll
            for (int k = 0; k < 4; k++) acc[mg][n][k] = 0.f;
    float zacc[2][4] = {{0.f,0.f,0.f,0.f},{0.f,0.f,0.f,0.f}};

    // ---- prologue: stage tile0, prefetch tile1 ----
    uint4 nva, nvb;
    if (stager) {
        nva = *(const uint4*)(hp + q4 * 8);
        nvb = *(const uint4*)(hp + 32 + q4 * 8);
        unsigned char* ba = &Bsm[0][0][sd * 64];
        unsigned char* bb = &Bsm[0][1][sd * 64];
        *(uint32_t*)(ba + (((0 ^ skey) << 4) + ppos)) = nva.x;
        *(uint32_t*)(ba + (((1 ^ skey) << 4) + ppos)) = nva.y;
        *(uint32_t*)(ba + (((2 ^ skey) << 4) + ppos)) = nva.z;
        *(uint32_t*)(ba + (((3 ^ skey) << 4) + ppos)) = nva.w;
        *(uint32_t*)(bb + (((0 ^ skey) << 4) + ppos)) = nvb.x;
        *(uint32_t*)(bb + (((1 ^ skey) << 4) + ppos)) = nvb.y;
        *(uint32_t*)(bb + (((2 ^ skey) << 4) + ppos)) = nvb.z;
        *(uint32_t*)(bb + (((3 ^ skey) << 4) + ppos)) = nvb.w;
        nva = *(const uint4*)(hp + KT2 + q4 * 8);
        nvb = *(const uint4*)(hp + KT2 + 32 + q4 * 8);
    }
    if (tid < KT2)
        QQ[0][tid] = make_float2(g_Q[head * NN + tid], g_q[head * NN + tid]);
    unsigned cm[4], nm[4];
#pragma unroll
    for (int k = 0; k < 4; k++) {
        cm[k] = mp[k][jh];
        nm[k] = mp[k][2 + jh];
    }
    float nQ = 0.f, nq = 0.f;
    if (tid < KT2) {
        nQ = g_Q[head * NN + KT2 + tid];
        nq = g_q[head * NN + KT2 + tid];
    }
    __syncthreads();

    for (int t = 0; t < NT2; t++) {
        const int buf = t & 1;
        const int nbuf = buf ^ 1;

        if (t + 1 < NT2) {
            if (stager) {
                unsigned char* ba = &Bsm[nbuf][0][sd * 64];
                unsigned char* bb = &Bsm[nbuf][1][sd * 64];
                *(uint32_t*)(ba + (((0 ^ skey) << 4) + ppos)) = nva.x;
                *(uint32_t*)(ba + (((1 ^ skey) << 4) + ppos)) = nva.y;
                *(uint32_t*)(ba + (((2 ^ skey) << 4) + ppos)) = nva.z;
                *(uint32_t*)(ba + (((3 ^ skey) << 4) + ppos)) = nva.w;
                *(uint32_t*)(bb + (((0 ^ skey) << 4) + ppos)) = nvb.x;
                *(uint32_t*)(bb + (((1 ^ skey) << 4) + ppos)) = nvb.y;
                *(uint32_t*)(bb + (((2 ^ skey) << 4) + ppos)) = nvb.z;
                *(uint32_t*)(bb + (((3 ^ skey) << 4) + ppos)) = nvb.w;
            }
            if (tid < KT2) QQ[nbuf][tid] = make_float2(nQ, nq);
        }

        // ---- A fragments: 2 m-frags (rows gr+mg*16, +8), this warp's j-half ----
        uint32_t A[2][2][4];
#pragma unroll
        for (int mg = 0; mg < 2; mg++) {
            const unsigned ma = cm[2 * mg];
            const unsigned mb = cm[2 * mg + 1];
            const float Pa = Ps[2 * mg], pa = ps[2 * mg];
            const float Pb = Ps[2 * mg + 1], pb = ps[2 * mg + 1];
#pragma unroll
            for (int s = 0; s < 2; s++) {
                const int ja = 16 * s + 2 * c;
                const int jq = jh * 32 + ja;
                float2 qa0 = QQ[buf][jq];
                float2 qa1 = QQ[buf][jq + 1];
                float2 qb0 = QQ[buf][jq + 8];
                float2 qb1 = QQ[buf][jq + 9];
                float wa0 = fmaxf(Pa * qa0.x, pa * qa0.y); wa0 = ((ma >> ja)       & 1u) ? wa0 : 0.f;
                float wa1 = fmaxf(Pa * qa1.x, pa * qa1.y); wa1 = ((ma >> (ja + 1)) & 1u) ? wa1 : 0.f;
                float wa8 = fmaxf(Pa * qb0.x, pa * qb0.y); wa8 = ((ma >> (ja + 8)) & 1u) ? wa8 : 0.f;
                float wa9 = fmaxf(Pa * qb1.x, pa * qb1.y); wa9 = ((ma >> (ja + 9)) & 1u) ? wa9 : 0.f;
                float wb0 = fmaxf(Pb * qa0.x, pb * qa0.y); wb0 = ((mb >> ja)       & 1u) ? wb0 : 0.f;
                float wb1 = fmaxf(Pb * qa1.x, pb * qa1.y); wb1 = ((mb >> (ja + 1)) & 1u) ? wb1 : 0.f;
                float wb8 = fmaxf(Pb * qb0.x, pb * qb0.y); wb8 = ((mb >> (ja + 8)) & 1u) ? wb8 : 0.f;
                float wb9 = fmaxf(Pb * qb1.x, pb * qb1.y); wb9 = ((mb >> (ja + 9)) & 1u) ? wb9 : 0.f;
                A[mg][s][0] = packh2(wa1, wa0);
                A[mg][s][1] = packh2(wb1, wb0);
                A[mg][s][2] = packh2(wa9, wa8);
                A[mg][s][3] = packh2(wb9, wb8);
            }
        }

        // rotate masks, prefetch tile t+2
#pragma unroll
        for (int k = 0; k < 4; k++) cm[k] = nm[k];
        if (t + 2 < NT2) {
            const int j0 = (t + 2) * KT2;
            if (stager) {
                nva = *(const uint4*)(hp + j0 + q4 * 8);
                nvb = *(const uint4*)(hp + j0 + 32 + q4 * 8);
            }
#pragma unroll
            for (int k = 0; k < 4; k++) nm[k] = mp[k][2 * (t + 2) + jh];
            if (tid < KT2) {
                nQ = g_Q[head * NN + j0 + tid];
                nq = g_q[head * NN + j0 + tid];
            }
        }

        // ---- B loads (only this warp's j-half) + MMA ----
#pragma unroll
        for (int nt = 0; nt < 8; nt++) {
            const int d = nt * 8 + gr;
            const uint32_t off = (uint32_t)(d * 64 + ((c ^ (gr & 3)) << 4));
            uint4 v = *(const uint4*)(&Bsm[buf][jh][off]);
            mma_f16(acc[0][nt], A[0][0], v.x, v.y);
            mma_f16(acc[0][nt], A[0][1], v.z, v.w);
            mma_f16(acc[1][nt], A[1][0], v.x, v.y);
            mma_f16(acc[1][nt], A[1][1], v.z, v.w);
        }
        mma_f16(zacc[0], A[0][0], ONE2, ONE2);
        mma_f16(zacc[0], A[0][1], ONE2, ONE2);
        mma_f16(zacc[1], A[1][0], ONE2, ONE2);
        mma_f16(zacc[1], A[1][1], ONE2, ONE2);
        __syncthreads();
    }

    // ---- combine the two j-halves ----
#pragma unroll
    for (int mg = 0; mg < 2; mg++) {
        const int la = ir * 32 + mg * 16 + gr;
        zsh[jh][la]     = zacc[mg][0];
        zsh[jh][la + 8] = zacc[mg][2];
    }
    __syncthreads();
    const int cb = c * 2;
    if (jh == 1) {
#pragma unroll
        for (int mg = 0; mg < 2; mg++) {
            const int la = ir * 32 + mg * 16 + gr;
            const float iz0 = 1.0f / (zacc[mg][0] + zsh[0][la]);
            const float iz1 = 1.0f / (zacc[mg][2] + zsh[0][la + 8]);
            float* o0 = out + (size_t)(i0 + la) * OF + head * HD + cb;
            float* o1 = o0 + 8 * OF;
#pragma unroll
            for (int nt = 0; nt < 8; nt++) {
                *(float2*)(o0 + nt * 8) = make_float2(acc[mg][nt][0] * iz0, acc[mg][nt][1] * iz0);
                *(float2*)(o1 + nt * 8) = make_float2(acc[mg][nt][2] * iz1, acc[mg][nt][3] * iz1);
            }
        }
    }
    __syncthreads();
    if (jh == 0) {
#pragma unroll
        for (int mg = 0; mg < 2; mg++) {
            const int la = ir * 32 + mg * 16 + gr;
            const float iz0 = 1.0f / (zacc[mg][0] + zsh[1][la]);
            const float iz1 = 1.0f / (zacc[mg][2] + zsh[1][la + 8]);
            float* o0 = out + (size_t)(i0 + la) * OF + head * HD + cb;
            float* o1 = o0 + 8 * OF;
#pragma unroll
            for (int nt = 0; nt < 8; nt++) {
                float2 v0 = *(float2*)(o0 + nt * 8);
                float2 v1 = *(float2*)(o1 + nt * 8);
                v0.x += acc[mg][nt][0] * iz0; v0.y += acc[mg][nt][1] * iz0;
                v1.x += acc[mg][nt][2] * iz1; v1.y += acc[mg][nt][3] * iz1;
                *(float2*)(o0 + nt * 8) = v0;
                *(float2*)(o1 + nt * 8) = v1;
            }
        }
    }
}

// ---------------- launch ----------------
extern "C" void kernel_launch(void* const* d_in, const int* in_sizes, int n_in,
                              void* d_out, int out_size) {
    const float* x     = (const float*)d_in[0];
    const int*   adj   = (const int*)d_in[1];
    const float* W     = (const float*)d_in[2];
    const float* a_src = (const float*)d_in[3];
    const float* a_dst = (const float*)d_in[4];
    float* out = (float*)d_out;

    fsplit_kernel<<<((NN + OF) * INF) / 2048, 256>>>(x, W);
    mask_kernel<<<(NN * (NN / 512) * 32) / 256, 256>>>(adj);
    gemm_kernel<<<dim3(NN / 96, OF / 128), 384>>>();
    htrans_kernel<<<dim3(NN / 32, NH), 256>>>(a_src, a_dst);
    attn_kernel<<<dim3(NN / MT, NH), 384>>>(out);
}